// round 1
// baseline (speedup 1.0000x reference)
#include <cuda_runtime.h>

#define BB 2
#define TT 2048
#define CCH 2048
#define NH 16
#define NKV 4
#define HD 128
#define MROWS (BB*TT)

// Scratch (no cudaMalloc allowed)
__device__ float g_q[(size_t)BB*NH*TT*HD];     // [B,H,T,HD]
__device__ float g_k[(size_t)BB*NKV*TT*HD];    // [B,KV,T,HD]
__device__ float g_v[(size_t)BB*NKV*TT*HD];    // [B,KV,T,HD]
__device__ float g_attn[(size_t)BB*TT*NH*HD];  // [B,T,H*HD]

// ---------------------------------------------------------------------------
// Generic 128x128x16 SIMT fp32 GEMM, 256 threads, 8x8 register tile.
// MODE 0: A = x [4096,2048], fused N=3072 (Wq 2048 | Wk 512 | Wv 512),
//         epilogue scatters into g_q / g_k / g_v head-major layouts.
// MODE 1: A = g_attn [4096,2048], W0 = Wo [2048,2048], epilogue -> out.
// ---------------------------------------------------------------------------
template<int MODE>
__global__ __launch_bounds__(256) void gemm_kernel(
    const float* __restrict__ A,
    const float* __restrict__ W0,
    const float* __restrict__ W1,
    const float* __restrict__ W2,
    float* __restrict__ out)
{
    const int tid = threadIdx.x;
    const int bm0 = blockIdx.y * 128;
    const int bn0 = blockIdx.x * 128;

    const float* Ap = (MODE == 0) ? A : g_attn;

    const float* Wp; int ldw, noff;
    if (MODE == 0) {
        if (bn0 < 2048)      { Wp = W0; ldw = 2048; noff = bn0; }
        else if (bn0 < 2560) { Wp = W1; ldw = 512;  noff = bn0 - 2048; }
        else                 { Wp = W2; ldw = 512;  noff = bn0 - 2560; }
    } else { Wp = W0; ldw = 2048; noff = bn0; }

    __shared__ float As[16][132];   // transposed A tile [k][m]
    __shared__ float Bs[16][132];   // B tile [k][n]

    const int tx = tid & 15;
    const int ty = tid >> 4;

    const int ar0 = tid >> 2,          ac0 = (tid & 3) * 4;
    const int ar1 = (tid + 256) >> 2,  ac1 = ((tid + 256) & 3) * 4;
    const int br0 = tid >> 5,          bc0 = (tid & 31) * 4;
    const int br1 = (tid + 256) >> 5,  bc1 = ((tid + 256) & 31) * 4;

    float4 ra0, ra1, rb0, rb1;

    // prologue: load tile 0
    {
        const int k0 = 0;
        ra0 = *(const float4*)&Ap[(size_t)(bm0 + ar0) * CCH + k0 + ac0];
        ra1 = *(const float4*)&Ap[(size_t)(bm0 + ar1) * CCH + k0 + ac1];
        rb0 = *(const float4*)&Wp[(size_t)(k0 + br0) * ldw + noff + bc0];
        rb1 = *(const float4*)&Wp[(size_t)(k0 + br1) * ldw + noff + bc1];
    }
    As[ac0+0][ar0] = ra0.x; As[ac0+1][ar0] = ra0.y; As[ac0+2][ar0] = ra0.z; As[ac0+3][ar0] = ra0.w;
    As[ac1+0][ar1] = ra1.x; As[ac1+1][ar1] = ra1.y; As[ac1+2][ar1] = ra1.z; As[ac1+3][ar1] = ra1.w;
    *(float4*)&Bs[br0][bc0] = rb0;
    *(float4*)&Bs[br1][bc1] = rb1;
    __syncthreads();

    float acc[8][8];
#pragma unroll
    for (int i = 0; i < 8; ++i)
#pragma unroll
        for (int j = 0; j < 8; ++j) acc[i][j] = 0.f;

    const int NIT = CCH / 16;
    for (int kt = 0; kt < NIT; ++kt) {
        if (kt + 1 < NIT) {
            const int k0 = (kt + 1) * 16;
            ra0 = *(const float4*)&Ap[(size_t)(bm0 + ar0) * CCH + k0 + ac0];
            ra1 = *(const float4*)&Ap[(size_t)(bm0 + ar1) * CCH + k0 + ac1];
            rb0 = *(const float4*)&Wp[(size_t)(k0 + br0) * ldw + noff + bc0];
            rb1 = *(const float4*)&Wp[(size_t)(k0 + br1) * ldw + noff + bc1];
        }
#pragma unroll
        for (int k = 0; k < 16; ++k) {
            float a_[8], b_[8];
            *(float4*)&a_[0] = *(const float4*)&As[k][ty * 4];
            *(float4*)&a_[4] = *(const float4*)&As[k][64 + ty * 4];
            *(float4*)&b_[0] = *(const float4*)&Bs[k][tx * 4];
            *(float4*)&b_[4] = *(const float4*)&Bs[k][64 + tx * 4];
#pragma unroll
            for (int i = 0; i < 8; ++i)
#pragma unroll
                for (int j = 0; j < 8; ++j)
                    acc[i][j] += a_[i] * b_[j];
        }
        if (kt + 1 < NIT) {
            __syncthreads();
            As[ac0+0][ar0] = ra0.x; As[ac0+1][ar0] = ra0.y; As[ac0+2][ar0] = ra0.z; As[ac0+3][ar0] = ra0.w;
            As[ac1+0][ar1] = ra1.x; As[ac1+1][ar1] = ra1.y; As[ac1+2][ar1] = ra1.z; As[ac1+3][ar1] = ra1.w;
            *(float4*)&Bs[br0][bc0] = rb0;
            *(float4*)&Bs[br1][bc1] = rb1;
            __syncthreads();
        }
    }

    int ml[8], nl[8];
#pragma unroll
    for (int i = 0; i < 4; ++i) {
        ml[i] = ty * 4 + i;  ml[i + 4] = 64 + ty * 4 + i;
        nl[i] = tx * 4 + i;  nl[i + 4] = 64 + tx * 4 + i;
    }

    if (MODE == 1) {
#pragma unroll
        for (int i = 0; i < 8; ++i) {
            const int m = bm0 + ml[i];
            float* orow = out + (size_t)m * 2048 + bn0;
#pragma unroll
            for (int j = 0; j < 8; ++j) orow[nl[j]] = acc[i][j];
        }
    } else {
        if (bn0 < 2048) {
            const int h = bn0 >> 7;
#pragma unroll
            for (int i = 0; i < 8; ++i) {
                const int m = bm0 + ml[i];
                const int b = m >> 11, t = m & 2047;
                float* dst = g_q + ((size_t)(b * NH + h) * TT + t) * HD;
#pragma unroll
                for (int j = 0; j < 8; ++j) dst[nl[j]] = acc[i][j];
            }
        } else if (bn0 < 2560) {
            const int kvh = (bn0 - 2048) >> 7;
#pragma unroll
            for (int i = 0; i < 8; ++i) {
                const int m = bm0 + ml[i];
                const int b = m >> 11, t = m & 2047;
                float* dst = g_k + ((size_t)(b * NKV + kvh) * TT + t) * HD;
#pragma unroll
                for (int j = 0; j < 8; ++j) dst[nl[j]] = acc[i][j];
            }
        } else {
            const int kvh = (bn0 - 2560) >> 7;
#pragma unroll
            for (int i = 0; i < 8; ++i) {
                const int m = bm0 + ml[i];
                const int b = m >> 11, t = m & 2047;
                float* dst = g_v + ((size_t)(b * NKV + kvh) * TT + t) * HD;
#pragma unroll
                for (int j = 0; j < 8; ++j) dst[nl[j]] = acc[i][j];
            }
        }
    }
}

// ---------------------------------------------------------------------------
// RoPE (in place on g_q, g_k). One thread per (bh, t, d<64) pair.
// out[d]    = x[d]*cos[d]    - x[d+64]*sin[d]
// out[d+64] = x[d+64]*cos[d+64] + x[d]*sin[d+64]
// ---------------------------------------------------------------------------
__global__ void rope_kernel(const float* __restrict__ cosp,
                            const float* __restrict__ sinp)
{
    const int i = blockIdx.x * 256 + threadIdx.x;
    const int nq = BB * NH * TT * 64;
    const int nk = BB * NKV * TT * 64;
    float* base;
    int t, d;
    if (i < nq) {
        d = i & 63; t = (i >> 6) & 2047;
        const int bh = i >> 17;
        base = g_q + ((size_t)bh * TT + t) * HD;
    } else if (i < nq + nk) {
        const int i2 = i - nq;
        d = i2 & 63; t = (i2 >> 6) & 2047;
        const int bkv = i2 >> 17;
        base = g_k + ((size_t)bkv * TT + t) * HD;
    } else return;

    const float c0 = cosp[t * HD + d],      s0 = sinp[t * HD + d];
    const float c1 = cosp[t * HD + d + 64], s1 = sinp[t * HD + d + 64];
    const float x0 = base[d], x1 = base[d + 64];
    base[d]      = x0 * c0 - x1 * s0;
    base[d + 64] = x1 * c1 + x0 * s1;
}

// ---------------------------------------------------------------------------
// Flash attention: block = 256 threads = 64 quads; quad q handles query row
// qtile*64+q. Each quad thread owns float4 chunks lane4+4j (j=0..7) of HD=128.
// K/V tiles of 64 keys live in 64 KB dynamic smem. Online softmax.
// ---------------------------------------------------------------------------
__global__ __launch_bounds__(256) void attn_kernel()
{
    extern __shared__ float sh[];
    float* Ks = sh;               // [64][128]
    float* Vs = sh + 64 * 128;    // [64][128]

    const int tid   = threadIdx.x;
    const int qtile = blockIdx.x;
    const int bh    = blockIdx.y;
    const int b     = bh >> 4;
    const int h     = bh & 15;
    const int kvh   = h >> 2;

    const float* qb = g_q + (size_t)bh * TT * HD;
    const float* kb = g_k + (size_t)(b * NKV + kvh) * TT * HD;
    const float* vb = g_v + (size_t)(b * NKV + kvh) * TT * HD;

    const int lane4 = tid & 3;
    const int row   = qtile * 64 + (tid >> 2);
    const float scale = 0.08838834764831845f;  // 1/sqrt(128)

    float4 q4[8];
#pragma unroll
    for (int j = 0; j < 8; ++j) {
        float4 v = *(const float4*)&qb[(size_t)row * HD + (lane4 + 4 * j) * 4];
        v.x *= scale; v.y *= scale; v.z *= scale; v.w *= scale;
        q4[j] = v;
    }

    float m = -1e30f, l = 0.f;
    float4 o4[8];
#pragma unroll
    for (int j = 0; j < 8; ++j) o4[j] = make_float4(0.f, 0.f, 0.f, 0.f);

    for (int kt = 0; kt <= qtile; ++kt) {
        // cooperative K/V tile load (float4, coalesced)
#pragma unroll
        for (int i = 0; i < 8; ++i) {
            const int idx = tid + 256 * i;
            const int r = idx >> 5, c4 = (idx & 31) * 4;
            *(float4*)&Ks[r * 128 + c4] = *(const float4*)&kb[(size_t)(kt * 64 + r) * HD + c4];
            *(float4*)&Vs[r * 128 + c4] = *(const float4*)&vb[(size_t)(kt * 64 + r) * HD + c4];
        }
        __syncthreads();

        const bool last = (kt == qtile);
        float sreg[16];
#pragma unroll 4
        for (int c = 0; c < 64; ++c) {
            const float4* kr = (const float4*)&Ks[c * 128];
            float s = 0.f;
#pragma unroll
            for (int j = 0; j < 8; ++j) {
                const float4 kv = kr[lane4 + 4 * j];
                s += q4[j].x * kv.x + q4[j].y * kv.y + q4[j].z * kv.z + q4[j].w * kv.w;
            }
            s += __shfl_xor_sync(0xffffffffu, s, 1);
            s += __shfl_xor_sync(0xffffffffu, s, 2);
            if (last && (kt * 64 + c > row)) s = -1e30f;
            if ((c & 3) == lane4) sreg[c >> 2] = s;
        }

        float tmax = sreg[0];
#pragma unroll
        for (int j = 1; j < 16; ++j) tmax = fmaxf(tmax, sreg[j]);
        tmax = fmaxf(tmax, __shfl_xor_sync(0xffffffffu, tmax, 1));
        tmax = fmaxf(tmax, __shfl_xor_sync(0xffffffffu, tmax, 2));

        const float mnew = fmaxf(m, tmax);
        const float corr = __expf(m - mnew);
        l *= corr;
#pragma unroll
        for (int j = 0; j < 8; ++j) {
            o4[j].x *= corr; o4[j].y *= corr; o4[j].z *= corr; o4[j].w *= corr;
        }
#pragma unroll
        for (int j = 0; j < 16; ++j) sreg[j] = __expf(sreg[j] - mnew);
        m = mnew;

#pragma unroll 4
        for (int c = 0; c < 64; ++c) {
            const float p = __shfl_sync(0xffffffffu, sreg[c >> 2], c & 3, 4);
            l += p;
            const float4* vr = (const float4*)&Vs[c * 128];
#pragma unroll
            for (int j = 0; j < 8; ++j) {
                const float4 vv = vr[lane4 + 4 * j];
                o4[j].x += p * vv.x; o4[j].y += p * vv.y;
                o4[j].z += p * vv.z; o4[j].w += p * vv.w;
            }
        }
        __syncthreads();
    }

    const float inv = 1.f / l;
    float* ob = g_attn + ((size_t)(b * TT + row)) * (NH * HD) + h * HD;
#pragma unroll
    for (int j = 0; j < 8; ++j) {
        float4 v = o4[j];
        v.x *= inv; v.y *= inv; v.z *= inv; v.w *= inv;
        *(float4*)&ob[(lane4 + 4 * j) * 4] = v;
    }
}

// ---------------------------------------------------------------------------
extern "C" void kernel_launch(void* const* d_in, const int* in_sizes, int n_in,
                              void* d_out, int out_size)
{
    const float* x    = (const float*)d_in[0];
    const float* cosp = (const float*)d_in[1];
    const float* sinp = (const float*)d_in[2];
    const float* Wq   = (const float*)d_in[3];
    const float* Wk   = (const float*)d_in[4];
    const float* Wv   = (const float*)d_in[5];
    const float* Wo   = (const float*)d_in[6];
    float* out = (float*)d_out;

    cudaFuncSetAttribute(attn_kernel,
                         cudaFuncAttributeMaxDynamicSharedMemorySize, 65536);

    // 1. fused QKV projection (N = 2048 + 512 + 512)
    gemm_kernel<0><<<dim3(24, 32), 256>>>(x, Wq, Wk, Wv, nullptr);

    // 2. RoPE on q and k
    const int nrope = BB * NH * TT * 64 + BB * NKV * TT * 64;
    rope_kernel<<<(nrope + 255) / 256, 256>>>(cosp, sinp);

    // 3. causal GQA flash attention
    attn_kernel<<<dim3(TT / 64, BB * NH), 256, 65536>>>();

    // 4. output projection
    gemm_kernel<1><<<dim3(16, 32), 256>>>(nullptr, Wo, nullptr, nullptr, out);
}

// round 2
// speedup vs baseline: 1.3155x; 1.3155x over previous
#include <cuda_runtime.h>

#define BB 2
#define TT 2048
#define CCH 2048
#define NH 16
#define NKV 4
#define HD 128

// Scratch (no cudaMalloc allowed)
__device__ float g_q[(size_t)BB*NH*TT*HD];     // [B,H,T,HD]
__device__ float g_k[(size_t)BB*NKV*TT*HD];    // [B,KV,T,HD]
__device__ float g_v[(size_t)BB*NKV*TT*HD];    // [B,KV,T,HD]
__device__ float g_attn[(size_t)BB*TT*NH*HD];  // [B,T,H*HD]

// ---------------------------------------------------------------------------
// Generic 128x128x16 SIMT fp32 GEMM, 256 threads, 8x8 register tile.
// ---------------------------------------------------------------------------
template<int MODE>
__global__ __launch_bounds__(256) void gemm_kernel(
    const float* __restrict__ A,
    const float* __restrict__ W0,
    const float* __restrict__ W1,
    const float* __restrict__ W2,
    float* __restrict__ out)
{
    const int tid = threadIdx.x;
    const int bm0 = blockIdx.y * 128;
    const int bn0 = blockIdx.x * 128;

    const float* Ap = (MODE == 0) ? A : g_attn;

    const float* Wp; int ldw, noff;
    if (MODE == 0) {
        if (bn0 < 2048)      { Wp = W0; ldw = 2048; noff = bn0; }
        else if (bn0 < 2560) { Wp = W1; ldw = 512;  noff = bn0 - 2048; }
        else                 { Wp = W2; ldw = 512;  noff = bn0 - 2560; }
    } else { Wp = W0; ldw = 2048; noff = bn0; }

    __shared__ float As[16][132];
    __shared__ float Bs[16][132];

    const int tx = tid & 15;
    const int ty = tid >> 4;

    const int ar0 = tid >> 2,          ac0 = (tid & 3) * 4;
    const int ar1 = (tid + 256) >> 2,  ac1 = ((tid + 256) & 3) * 4;
    const int br0 = tid >> 5,          bc0 = (tid & 31) * 4;
    const int br1 = (tid + 256) >> 5,  bc1 = ((tid + 256) & 31) * 4;

    float4 ra0, ra1, rb0, rb1;

    {
        const int k0 = 0;
        ra0 = *(const float4*)&Ap[(size_t)(bm0 + ar0) * CCH + k0 + ac0];
        ra1 = *(const float4*)&Ap[(size_t)(bm0 + ar1) * CCH + k0 + ac1];
        rb0 = *(const float4*)&Wp[(size_t)(k0 + br0) * ldw + noff + bc0];
        rb1 = *(const float4*)&Wp[(size_t)(k0 + br1) * ldw + noff + bc1];
    }
    As[ac0+0][ar0] = ra0.x; As[ac0+1][ar0] = ra0.y; As[ac0+2][ar0] = ra0.z; As[ac0+3][ar0] = ra0.w;
    As[ac1+0][ar1] = ra1.x; As[ac1+1][ar1] = ra1.y; As[ac1+2][ar1] = ra1.z; As[ac1+3][ar1] = ra1.w;
    *(float4*)&Bs[br0][bc0] = rb0;
    *(float4*)&Bs[br1][bc1] = rb1;
    __syncthreads();

    float acc[8][8];
#pragma unroll
    for (int i = 0; i < 8; ++i)
#pragma unroll
        for (int j = 0; j < 8; ++j) acc[i][j] = 0.f;

    const int NIT = CCH / 16;
    for (int kt = 0; kt < NIT; ++kt) {
        if (kt + 1 < NIT) {
            const int k0 = (kt + 1) * 16;
            ra0 = *(const float4*)&Ap[(size_t)(bm0 + ar0) * CCH + k0 + ac0];
            ra1 = *(const float4*)&Ap[(size_t)(bm0 + ar1) * CCH + k0 + ac1];
            rb0 = *(const float4*)&Wp[(size_t)(k0 + br0) * ldw + noff + bc0];
            rb1 = *(const float4*)&Wp[(size_t)(k0 + br1) * ldw + noff + bc1];
        }
#pragma unroll
        for (int k = 0; k < 16; ++k) {
            float a_[8], b_[8];
            *(float4*)&a_[0] = *(const float4*)&As[k][ty * 4];
            *(float4*)&a_[4] = *(const float4*)&As[k][64 + ty * 4];
            *(float4*)&b_[0] = *(const float4*)&Bs[k][tx * 4];
            *(float4*)&b_[4] = *(const float4*)&Bs[k][64 + tx * 4];
#pragma unroll
            for (int i = 0; i < 8; ++i)
#pragma unroll
                for (int j = 0; j < 8; ++j)
                    acc[i][j] += a_[i] * b_[j];
        }
        if (kt + 1 < NIT) {
            __syncthreads();
            As[ac0+0][ar0] = ra0.x; As[ac0+1][ar0] = ra0.y; As[ac0+2][ar0] = ra0.z; As[ac0+3][ar0] = ra0.w;
            As[ac1+0][ar1] = ra1.x; As[ac1+1][ar1] = ra1.y; As[ac1+2][ar1] = ra1.z; As[ac1+3][ar1] = ra1.w;
            *(float4*)&Bs[br0][bc0] = rb0;
            *(float4*)&Bs[br1][bc1] = rb1;
            __syncthreads();
        }
    }

    int ml[8], nl[8];
#pragma unroll
    for (int i = 0; i < 4; ++i) {
        ml[i] = ty * 4 + i;  ml[i + 4] = 64 + ty * 4 + i;
        nl[i] = tx * 4 + i;  nl[i + 4] = 64 + tx * 4 + i;
    }

    if (MODE == 1) {
#pragma unroll
        for (int i = 0; i < 8; ++i) {
            const int m = bm0 + ml[i];
            float* orow = out + (size_t)m * 2048 + bn0;
#pragma unroll
            for (int j = 0; j < 8; ++j) orow[nl[j]] = acc[i][j];
        }
    } else {
        if (bn0 < 2048) {
            const int h = bn0 >> 7;
#pragma unroll
            for (int i = 0; i < 8; ++i) {
                const int m = bm0 + ml[i];
                const int b = m >> 11, t = m & 2047;
                float* dst = g_q + ((size_t)(b * NH + h) * TT + t) * HD;
#pragma unroll
                for (int j = 0; j < 8; ++j) dst[nl[j]] = acc[i][j];
            }
        } else if (bn0 < 2560) {
            const int kvh = (bn0 - 2048) >> 7;
#pragma unroll
            for (int i = 0; i < 8; ++i) {
                const int m = bm0 + ml[i];
                const int b = m >> 11, t = m & 2047;
                float* dst = g_k + ((size_t)(b * NKV + kvh) * TT + t) * HD;
#pragma unroll
                for (int j = 0; j < 8; ++j) dst[nl[j]] = acc[i][j];
            }
        } else {
            const int kvh = (bn0 - 2560) >> 7;
#pragma unroll
            for (int i = 0; i < 8; ++i) {
                const int m = bm0 + ml[i];
                const int b = m >> 11, t = m & 2047;
                float* dst = g_v + ((size_t)(b * NKV + kvh) * TT + t) * HD;
#pragma unroll
                for (int j = 0; j < 8; ++j) dst[nl[j]] = acc[i][j];
            }
        }
    }
}

// ---------------------------------------------------------------------------
// RoPE (in place on g_q, g_k).
// ---------------------------------------------------------------------------
__global__ void rope_kernel(const float* __restrict__ cosp,
                            const float* __restrict__ sinp)
{
    const int i = blockIdx.x * 256 + threadIdx.x;
    const int nq = BB * NH * TT * 64;
    const int nk = BB * NKV * TT * 64;
    float* base;
    int t, d;
    if (i < nq) {
        d = i & 63; t = (i >> 6) & 2047;
        const int bh = i >> 17;
        base = g_q + ((size_t)bh * TT + t) * HD;
    } else if (i < nq + nk) {
        const int i2 = i - nq;
        d = i2 & 63; t = (i2 >> 6) & 2047;
        const int bkv = i2 >> 17;
        base = g_k + ((size_t)bkv * TT + t) * HD;
    } else return;

    const float c0 = cosp[t * HD + d],      s0 = sinp[t * HD + d];
    const float c1 = cosp[t * HD + d + 64], s1 = sinp[t * HD + d + 64];
    const float x0 = base[d], x1 = base[d + 64];
    base[d]      = x0 * c0 - x1 * s0;
    base[d + 64] = x1 * c1 + x0 * s1;
}

// ---------------------------------------------------------------------------
// Flash attention, GEMM-style SIMT.
// CTA: 256 threads (tx 0..15, ty 0..15), 128 q-rows x 64-key tiles.
// Thread tile: S = 8 rows x 4 cols, O = 8 rows x 8 dims.
// Smem (floats):
//   Qs: float4 [32 d4][128 r]  (16384 f)  d4-major -> conflict-free MMA reads
//   Ks: float4 [32 d4][64 c]   ( 8192 f)
//   Vs: float4 [64 c][32 d4]   ( 8192 f)  row-major
//   Ps: float  [64 c][129]     ( 8256 f)  P transposed, pitch 129
// ---------------------------------------------------------------------------
#define QS_OFF 0
#define KS_OFF 16384
#define VS_OFF 24576
#define PS_OFF 32768
#define ATTN_SMEM_FLOATS (32768 + 64*129)

__global__ __launch_bounds__(256) void attn_kernel()
{
    extern __shared__ float sh[];
    float4* Qs = (float4*)(sh + QS_OFF);
    float4* Ks = (float4*)(sh + KS_OFF);
    float4* Vs = (float4*)(sh + VS_OFF);
    float*  Ps = sh + PS_OFF;

    const int tid = threadIdx.x;
    const int tx = tid & 15, ty = tid >> 4;
    const int qt = (int)gridDim.x - 1 - (int)blockIdx.x;   // heavy tiles first
    const int bh = blockIdx.y;
    const int b = bh >> 4, h = bh & 15, kvh = h >> 2;

    const float4* qb4 = (const float4*)(g_q + (size_t)bh * TT * HD);
    const float4* kb4 = (const float4*)(g_k + (size_t)(b * NKV + kvh) * TT * HD);
    const float4* vb4 = (const float4*)(g_v + (size_t)(b * NKV + kvh) * TT * HD);

    const float scale = 0.08838834764831845f;  // 1/sqrt(128)

    // Q tile: Qs[d4][r], pre-scaled
#pragma unroll
    for (int i = 0; i < 16; ++i) {
        const int idx = i * 256 + tid;
        const int r = idx & 127, d4 = idx >> 7;
        float4 v = qb4[(size_t)(qt * 128 + r) * 32 + d4];
        v.x *= scale; v.y *= scale; v.z *= scale; v.w *= scale;
        Qs[d4 * 128 + r] = v;
    }

    float o[8][8];
    float m[8], l[8];
#pragma unroll
    for (int i = 0; i < 8; ++i) {
        m[i] = -1e30f; l[i] = 0.f;
#pragma unroll
        for (int d = 0; d < 8; ++d) o[i][d] = 0.f;
    }

    const int ntiles = 2 * qt + 2;
    for (int kt = 0; kt < ntiles; ++kt) {
        // K tile: Ks[d4][c]
#pragma unroll
        for (int i = 0; i < 8; ++i) {
            const int idx = i * 256 + tid;
            const int c = idx & 63, d4 = idx >> 6;
            Ks[d4 * 64 + c] = kb4[(size_t)(kt * 64 + c) * 32 + d4];
        }
        // V tile: Vs[c][d4] (coalesced)
#pragma unroll
        for (int i = 0; i < 8; ++i) {
            const int idx = i * 256 + tid;
            const int d4 = idx & 31, c = idx >> 5;
            Vs[c * 32 + d4] = vb4[(size_t)(kt * 64 + c) * 32 + d4];
        }
        __syncthreads();

        // S = Q K^T (thread: rows ty*8..+7, cols tx*4..+3)
        float s[8][4];
#pragma unroll
        for (int i = 0; i < 8; ++i)
#pragma unroll
            for (int j = 0; j < 4; ++j) s[i][j] = 0.f;

#pragma unroll 2
        for (int d4 = 0; d4 < 32; ++d4) {
            const float4 b0 = Ks[d4 * 64 + tx * 4 + 0];
            const float4 b1 = Ks[d4 * 64 + tx * 4 + 1];
            const float4 b2 = Ks[d4 * 64 + tx * 4 + 2];
            const float4 b3 = Ks[d4 * 64 + tx * 4 + 3];
#pragma unroll
            for (int i = 0; i < 8; ++i) {
                const float4 a = Qs[d4 * 128 + ty * 8 + i];
                s[i][0] += a.x*b0.x + a.y*b0.y + a.z*b0.z + a.w*b0.w;
                s[i][1] += a.x*b1.x + a.y*b1.y + a.z*b1.z + a.w*b1.w;
                s[i][2] += a.x*b2.x + a.y*b2.y + a.z*b2.z + a.w*b2.w;
                s[i][3] += a.x*b3.x + a.y*b3.y + a.z*b3.z + a.w*b3.w;
            }
        }

        // causal mask on the two diagonal tiles
        if (kt >= 2 * qt) {
#pragma unroll
            for (int i = 0; i < 8; ++i) {
                const int row = qt * 128 + ty * 8 + i;
#pragma unroll
                for (int j = 0; j < 4; ++j) {
                    if (kt * 64 + tx * 4 + j > row) s[i][j] = -1e30f;
                }
            }
        }

        // online softmax per row; write P^T to smem
#pragma unroll
        for (int i = 0; i < 8; ++i) {
            float mx = fmaxf(fmaxf(s[i][0], s[i][1]), fmaxf(s[i][2], s[i][3]));
            mx = fmaxf(mx, __shfl_xor_sync(0xffffffffu, mx, 1, 16));
            mx = fmaxf(mx, __shfl_xor_sync(0xffffffffu, mx, 2, 16));
            mx = fmaxf(mx, __shfl_xor_sync(0xffffffffu, mx, 4, 16));
            mx = fmaxf(mx, __shfl_xor_sync(0xffffffffu, mx, 8, 16));
            const float mn = fmaxf(m[i], mx);
            const float corr = __expf(m[i] - mn);
            m[i] = mn;
            float rs = 0.f;
#pragma unroll
            for (int j = 0; j < 4; ++j) {
                s[i][j] = __expf(s[i][j] - mn);
                rs += s[i][j];
            }
            rs += __shfl_xor_sync(0xffffffffu, rs, 1, 16);
            rs += __shfl_xor_sync(0xffffffffu, rs, 2, 16);
            rs += __shfl_xor_sync(0xffffffffu, rs, 4, 16);
            rs += __shfl_xor_sync(0xffffffffu, rs, 8, 16);
            l[i] = l[i] * corr + rs;
#pragma unroll
            for (int d = 0; d < 8; ++d) o[i][d] *= corr;
#pragma unroll
            for (int j = 0; j < 4; ++j)
                Ps[(tx * 4 + j) * 129 + ty * 8 + i] = s[i][j];
        }
        __syncthreads();

        // O += P V (thread: rows ty*8..+7, dims tx*8..+7)
#pragma unroll 2
        for (int c = 0; c < 64; ++c) {
            const float4 v0 = Vs[c * 32 + tx * 2 + 0];
            const float4 v1 = Vs[c * 32 + tx * 2 + 1];
#pragma unroll
            for (int i = 0; i < 8; ++i) {
                const float p = Ps[c * 129 + ty * 8 + i];
                o[i][0] += p * v0.x; o[i][1] += p * v0.y;
                o[i][2] += p * v0.z; o[i][3] += p * v0.w;
                o[i][4] += p * v1.x; o[i][5] += p * v1.y;
                o[i][6] += p * v1.z; o[i][7] += p * v1.w;
            }
        }
        __syncthreads();
    }

    // epilogue
#pragma unroll
    for (int i = 0; i < 8; ++i) {
        const float inv = 1.f / l[i];
        const int row_g = qt * 128 + ty * 8 + i;
        float* ob = g_attn + ((size_t)(b * TT + row_g)) * (NH * HD) + h * HD + tx * 8;
        float4 w0 = make_float4(o[i][0]*inv, o[i][1]*inv, o[i][2]*inv, o[i][3]*inv);
        float4 w1 = make_float4(o[i][4]*inv, o[i][5]*inv, o[i][6]*inv, o[i][7]*inv);
        *(float4*)&ob[0] = w0;
        *(float4*)&ob[4] = w1;
    }
}

// ---------------------------------------------------------------------------
extern "C" void kernel_launch(void* const* d_in, const int* in_sizes, int n_in,
                              void* d_out, int out_size)
{
    const float* x    = (const float*)d_in[0];
    const float* cosp = (const float*)d_in[1];
    const float* sinp = (const float*)d_in[2];
    const float* Wq   = (const float*)d_in[3];
    const float* Wk   = (const float*)d_in[4];
    const float* Wv   = (const float*)d_in[5];
    const float* Wo   = (const float*)d_in[6];
    float* out = (float*)d_out;

    const int attn_smem = ATTN_SMEM_FLOATS * 4;
    cudaFuncSetAttribute(attn_kernel,
                         cudaFuncAttributeMaxDynamicSharedMemorySize, attn_smem);

    // 1. fused QKV projection (N = 2048 + 512 + 512)
    gemm_kernel<0><<<dim3(24, 32), 256>>>(x, Wq, Wk, Wv, nullptr);

    // 2. RoPE on q and k
    const int nrope = BB * NH * TT * 64 + BB * NKV * TT * 64;
    rope_kernel<<<(nrope + 255) / 256, 256>>>(cosp, sinp);

    // 3. causal GQA flash attention
    attn_kernel<<<dim3(TT / 128, BB * NH), 256, attn_smem>>>();

    // 4. output projection
    gemm_kernel<1><<<dim3(16, 32), 256>>>(nullptr, Wo, nullptr, nullptr, out);
}

// round 3
// speedup vs baseline: 1.7455x; 1.3269x over previous
#include <cuda_runtime.h>
#include <cuda_bf16.h>
#include <cstdint>

#define BB 2
#define TT 2048
#define CCH 2048
#define NH 16
#define NKV 4
#define HD 128
#define MTOT 4096
#define NQKV 3072

typedef __nv_bfloat16 bf16;

// ---- scratch (no cudaMalloc allowed) ----
__device__ bf16 g_xhi[(size_t)MTOT*CCH],  g_xlo[(size_t)MTOT*CCH];    // x split   [m][k]
__device__ bf16 g_wqkv_hi[(size_t)NQKV*CCH], g_wqkv_lo[(size_t)NQKV*CCH]; // W^T split [n][k]
__device__ bf16 g_wo_hi[(size_t)CCH*CCH], g_wo_lo[(size_t)CCH*CCH];   // Wo^T split [n][k]
__device__ bf16 g_ahi[(size_t)MTOT*CCH],  g_alo[(size_t)MTOT*CCH];    // attn out split [m][k]
__device__ float g_q[(size_t)BB*NH*TT*HD];
__device__ float g_k[(size_t)BB*NKV*TT*HD];
__device__ float g_v[(size_t)BB*NKV*TT*HD];

__device__ __forceinline__ void split2(float v, bf16& h, bf16& l) {
    h = __float2bfloat16(v);
    l = __float2bfloat16(v - __bfloat162float(h));
}

// ---------------------------------------------------------------------------
// Split / transpose conversion kernels
// ---------------------------------------------------------------------------
__global__ void split_x_kernel(const float* __restrict__ x) {
    const size_t i = (size_t)blockIdx.x * 256 + threadIdx.x;
    split2(x[i], g_xhi[i], g_xlo[i]);
}

// fused QKV weights, transposed: out[n][k], n in [0,3072)
__global__ void split_wqkv_kernel(const float* __restrict__ Wq,
                                  const float* __restrict__ Wk,
                                  const float* __restrict__ Wv) {
    const size_t i = (size_t)blockIdx.x * 256 + threadIdx.x;
    const int n = (int)(i >> 11);
    const int k = (int)(i & 2047);
    float v;
    if (n < 2048)      v = Wq[(size_t)k * 2048 + n];
    else if (n < 2560) v = Wk[(size_t)k * 512 + (n - 2048)];
    else               v = Wv[(size_t)k * 512 + (n - 2560)];
    split2(v, g_wqkv_hi[i], g_wqkv_lo[i]);
}

__global__ void split_wo_kernel(const float* __restrict__ Wo) {
    const size_t i = (size_t)blockIdx.x * 256 + threadIdx.x;
    const int n = (int)(i >> 11);
    const int k = (int)(i & 2047);
    split2(Wo[(size_t)k * 2048 + n], g_wo_hi[i], g_wo_lo[i]);
}

// ---------------------------------------------------------------------------
// MMA helpers
// ---------------------------------------------------------------------------
__device__ __forceinline__ void ldm_x4(unsigned r[4], const bf16* p) {
    uint32_t a = (uint32_t)__cvta_generic_to_shared(p);
    asm volatile("ldmatrix.sync.aligned.m8n8.x4.shared.b16 {%0,%1,%2,%3}, [%4];"
        : "=r"(r[0]), "=r"(r[1]), "=r"(r[2]), "=r"(r[3]) : "r"(a));
}

__device__ __forceinline__ void mma16816(float c[4],
    unsigned a0, unsigned a1, unsigned a2, unsigned a3,
    unsigned b0, unsigned b1)
{
    asm volatile(
        "mma.sync.aligned.m16n8k16.row.col.f32.bf16.bf16.f32 "
        "{%0,%1,%2,%3},{%4,%5,%6,%7},{%8,%9},{%0,%1,%2,%3};"
        : "+f"(c[0]), "+f"(c[1]), "+f"(c[2]), "+f"(c[3])
        : "r"(a0), "r"(a1), "r"(a2), "r"(a3), "r"(b0), "r"(b1));
}

// ---------------------------------------------------------------------------
// Tensor-core split-bf16 GEMM: 128x128 tile, BK=32, 256 threads (8 warps 2x4).
// A [m][k] bf16 hi/lo, B [n][k] bf16 hi/lo (both K-major -> plain ldmatrix).
// D = Ahi*Bhi + Ahi*Blo + Alo*Bhi (fp32 accum).
// MODE 0: A=x, B=Wqkv^T, scatter to g_q/g_k/g_v. MODE 1: A=attn, B=Wo^T -> out.
// ---------------------------------------------------------------------------
#define SPITCH 40  // 32 + 8 pad (keeps 16B alignment, conflict-free ldmatrix)

template<int MODE>
__global__ __launch_bounds__(256) void gemm_tc(float* __restrict__ out)
{
    __shared__ bf16 sAh[128 * SPITCH], sAl[128 * SPITCH];
    __shared__ bf16 sBh[128 * SPITCH], sBl[128 * SPITCH];

    const int tid  = threadIdx.x;
    const int lane = tid & 31;
    const int wid  = tid >> 5;
    const int bm = blockIdx.y * 128;
    const int bn = blockIdx.x * 128;
    const int mw = (wid >> 2) * 64;   // warp M offset (2 warps over M)
    const int nw = (wid & 3) * 32;    // warp N offset (4 warps over N)

    const bf16* Ah = (MODE == 0) ? g_xhi : g_ahi;
    const bf16* Al = (MODE == 0) ? g_xlo : g_alo;
    const bf16* Bh = (MODE == 0) ? g_wqkv_hi : g_wo_hi;
    const bf16* Bl = (MODE == 0) ? g_wqkv_lo : g_wo_lo;

    // loader mapping: item u = tid (+256): row=u>>2, quad q=u&3 (8 bf16 = 16B)
    const int lr = tid >> 2;
    const int lq = (tid & 3) * 8;

    float c[4][4][4];
#pragma unroll
    for (int i = 0; i < 4; ++i)
#pragma unroll
        for (int j = 0; j < 4; ++j)
#pragma unroll
            for (int e = 0; e < 4; ++e) c[i][j][e] = 0.f;

    uint4 pAh[2], pAl[2], pBh[2], pBl[2];

#define GLOAD(k0)                                                              \
    do {                                                                       \
        pAh[0] = *(const uint4*)(Ah + (size_t)(bm + lr)      * CCH + (k0) + lq); \
        pAh[1] = *(const uint4*)(Ah + (size_t)(bm + lr + 64) * CCH + (k0) + lq); \
        pAl[0] = *(const uint4*)(Al + (size_t)(bm + lr)      * CCH + (k0) + lq); \
        pAl[1] = *(const uint4*)(Al + (size_t)(bm + lr + 64) * CCH + (k0) + lq); \
        pBh[0] = *(const uint4*)(Bh + (size_t)(bn + lr)      * CCH + (k0) + lq); \
        pBh[1] = *(const uint4*)(Bh + (size_t)(bn + lr + 64) * CCH + (k0) + lq); \
        pBl[0] = *(const uint4*)(Bl + (size_t)(bn + lr)      * CCH + (k0) + lq); \
        pBl[1] = *(const uint4*)(Bl + (size_t)(bn + lr + 64) * CCH + (k0) + lq); \
    } while (0)

#define SSTORE()                                                               \
    do {                                                                       \
        *(uint4*)&sAh[lr * SPITCH + lq]        = pAh[0];                       \
        *(uint4*)&sAh[(lr + 64) * SPITCH + lq] = pAh[1];                       \
        *(uint4*)&sAl[lr * SPITCH + lq]        = pAl[0];                       \
        *(uint4*)&sAl[(lr + 64) * SPITCH + lq] = pAl[1];                       \
        *(uint4*)&sBh[lr * SPITCH + lq]        = pBh[0];                       \
        *(uint4*)&sBh[(lr + 64) * SPITCH + lq] = pBh[1];                       \
        *(uint4*)&sBl[lr * SPITCH + lq]        = pBl[0];                       \
        *(uint4*)&sBl[(lr + 64) * SPITCH + lq] = pBl[1];                       \
    } while (0)

    GLOAD(0);
    SSTORE();
    __syncthreads();

    const int arow = ((lane >> 3) & 1) * 8 + (lane & 7);  // + mi*16
    const int acol = (lane >> 4) * 8;                     // + kk*16
    const int brow = (lane >> 4) * 8 + (lane & 7);        // + x*16
    const int bcol = ((lane >> 3) & 1) * 8;               // + kk*16

    const int NKT = CCH / 32;
    for (int kt = 0; kt < NKT; ++kt) {
        if (kt + 1 < NKT) GLOAD((kt + 1) * 32);

#pragma unroll
        for (int kk = 0; kk < 2; ++kk) {
            unsigned ah[4][4], al[4][4], bh[2][4], bl[2][4];
#pragma unroll
            for (int mi = 0; mi < 4; ++mi) {
                const int off = (mw + mi * 16 + arow) * SPITCH + kk * 16 + acol;
                ldm_x4(ah[mi], sAh + off);
                ldm_x4(al[mi], sAl + off);
            }
#pragma unroll
            for (int x = 0; x < 2; ++x) {
                const int off = (nw + x * 16 + brow) * SPITCH + kk * 16 + bcol;
                ldm_x4(bh[x], sBh + off);
                ldm_x4(bl[x], sBl + off);
            }
#pragma unroll
            for (int mi = 0; mi < 4; ++mi) {
#pragma unroll
                for (int nj = 0; nj < 4; ++nj) {
                    const int x = nj >> 1, y = (nj & 1) * 2;
                    mma16816(c[mi][nj], ah[mi][0], ah[mi][1], ah[mi][2], ah[mi][3],
                             bh[x][y], bh[x][y + 1]);
                    mma16816(c[mi][nj], ah[mi][0], ah[mi][1], ah[mi][2], ah[mi][3],
                             bl[x][y], bl[x][y + 1]);
                    mma16816(c[mi][nj], al[mi][0], al[mi][1], al[mi][2], al[mi][3],
                             bh[x][y], bh[x][y + 1]);
                }
            }
        }

        if (kt + 1 < NKT) {
            __syncthreads();
            SSTORE();
            __syncthreads();
        }
    }

    // epilogue
#pragma unroll
    for (int mi = 0; mi < 4; ++mi) {
#pragma unroll
        for (int nj = 0; nj < 4; ++nj) {
            const int m = bm + mw + mi * 16 + (lane >> 2);
            const int n = bn + nw + nj * 8 + 2 * (lane & 3);
            const float2 v0 = make_float2(c[mi][nj][0], c[mi][nj][1]);
            const float2 v1 = make_float2(c[mi][nj][2], c[mi][nj][3]);
            if (MODE == 1) {
                *(float2*)(out + (size_t)m * 2048 + n)       = v0;
                *(float2*)(out + (size_t)(m + 8) * 2048 + n) = v1;
            } else {
                const int b = m >> 11, t = m & 2047;
                const int d = n & 127;
                float* dst;
                if (n < 2048) {
                    const int h = n >> 7;
                    dst = g_q + ((size_t)(b * NH + h) * TT + t) * HD + d;
                } else if (n < 2560) {
                    const int kvh = (n - 2048) >> 7;
                    dst = g_k + ((size_t)(b * NKV + kvh) * TT + t) * HD + d;
                } else {
                    const int kvh = (n - 2560) >> 7;
                    dst = g_v + ((size_t)(b * NKV + kvh) * TT + t) * HD + d;
                }
                *(float2*)dst = v0;
                *(float2*)(dst + 8 * HD) = v1;   // m+8 -> t+8, same layout stride HD
            }
        }
    }
}

// ---------------------------------------------------------------------------
// RoPE (in place on g_q, g_k).
// ---------------------------------------------------------------------------
__global__ void rope_kernel(const float* __restrict__ cosp,
                            const float* __restrict__ sinp)
{
    const int i = blockIdx.x * 256 + threadIdx.x;
    const int nq = BB * NH * TT * 64;
    const int nk = BB * NKV * TT * 64;
    float* base;
    int t, d;
    if (i < nq) {
        d = i & 63; t = (i >> 6) & 2047;
        const int bh = i >> 17;
        base = g_q + ((size_t)bh * TT + t) * HD;
    } else if (i < nq + nk) {
        const int i2 = i - nq;
        d = i2 & 63; t = (i2 >> 6) & 2047;
        const int bkv = i2 >> 17;
        base = g_k + ((size_t)bkv * TT + t) * HD;
    } else return;

    const float c0 = cosp[t * HD + d],      s0 = sinp[t * HD + d];
    const float c1 = cosp[t * HD + d + 64], s1 = sinp[t * HD + d + 64];
    const float x0 = base[d], x1 = base[d + 64];
    base[d]      = x0 * c0 - x1 * s0;
    base[d + 64] = x1 * c1 + x0 * s1;
}

// ---------------------------------------------------------------------------
// Flash attention (SIMT GEMM-style, as R2), epilogue writes bf16 hi/lo.
// ---------------------------------------------------------------------------
#define QS_OFF 0
#define KS_OFF 16384
#define VS_OFF 24576
#define PS_OFF 32768
#define ATTN_SMEM_FLOATS (32768 + 64*129)

__global__ __launch_bounds__(256) void attn_kernel()
{
    extern __shared__ float sh[];
    float4* Qs = (float4*)(sh + QS_OFF);
    float4* Ks = (float4*)(sh + KS_OFF);
    float4* Vs = (float4*)(sh + VS_OFF);
    float*  Ps = sh + PS_OFF;

    const int tid = threadIdx.x;
    const int tx = tid & 15, ty = tid >> 4;
    const int qt = (int)gridDim.x - 1 - (int)blockIdx.x;
    const int bh = blockIdx.y;
    const int b = bh >> 4, h = bh & 15, kvh = h >> 2;

    const float4* qb4 = (const float4*)(g_q + (size_t)bh * TT * HD);
    const float4* kb4 = (const float4*)(g_k + (size_t)(b * NKV + kvh) * TT * HD);
    const float4* vb4 = (const float4*)(g_v + (size_t)(b * NKV + kvh) * TT * HD);

    const float scale = 0.08838834764831845f;

#pragma unroll
    for (int i = 0; i < 16; ++i) {
        const int idx = i * 256 + tid;
        const int r = idx & 127, d4 = idx >> 7;
        float4 v = qb4[(size_t)(qt * 128 + r) * 32 + d4];
        v.x *= scale; v.y *= scale; v.z *= scale; v.w *= scale;
        Qs[d4 * 128 + r] = v;
    }

    float o[8][8];
    float m[8], l[8];
#pragma unroll
    for (int i = 0; i < 8; ++i) {
        m[i] = -1e30f; l[i] = 0.f;
#pragma unroll
        for (int d = 0; d < 8; ++d) o[i][d] = 0.f;
    }

    const int ntiles = 2 * qt + 2;
    for (int kt = 0; kt < ntiles; ++kt) {
#pragma unroll
        for (int i = 0; i < 8; ++i) {
            const int idx = i * 256 + tid;
            const int cc = idx & 63, d4 = idx >> 6;
            Ks[d4 * 64 + cc] = kb4[(size_t)(kt * 64 + cc) * 32 + d4];
        }
#pragma unroll
        for (int i = 0; i < 8; ++i) {
            const int idx = i * 256 + tid;
            const int d4 = idx & 31, cc = idx >> 5;
            Vs[cc * 32 + d4] = vb4[(size_t)(kt * 64 + cc) * 32 + d4];
        }
        __syncthreads();

        float s[8][4];
#pragma unroll
        for (int i = 0; i < 8; ++i)
#pragma unroll
            for (int j = 0; j < 4; ++j) s[i][j] = 0.f;

#pragma unroll 2
        for (int d4 = 0; d4 < 32; ++d4) {
            const float4 b0 = Ks[d4 * 64 + tx * 4 + 0];
            const float4 b1 = Ks[d4 * 64 + tx * 4 + 1];
            const float4 b2 = Ks[d4 * 64 + tx * 4 + 2];
            const float4 b3 = Ks[d4 * 64 + tx * 4 + 3];
#pragma unroll
            for (int i = 0; i < 8; ++i) {
                const float4 a = Qs[d4 * 128 + ty * 8 + i];
                s[i][0] += a.x*b0.x + a.y*b0.y + a.z*b0.z + a.w*b0.w;
                s[i][1] += a.x*b1.x + a.y*b1.y + a.z*b1.z + a.w*b1.w;
                s[i][2] += a.x*b2.x + a.y*b2.y + a.z*b2.z + a.w*b2.w;
                s[i][3] += a.x*b3.x + a.y*b3.y + a.z*b3.z + a.w*b3.w;
            }
        }

        if (kt >= 2 * qt) {
#pragma unroll
            for (int i = 0; i < 8; ++i) {
                const int row = qt * 128 + ty * 8 + i;
#pragma unroll
                for (int j = 0; j < 4; ++j)
                    if (kt * 64 + tx * 4 + j > row) s[i][j] = -1e30f;
            }
        }

#pragma unroll
        for (int i = 0; i < 8; ++i) {
            float mx = fmaxf(fmaxf(s[i][0], s[i][1]), fmaxf(s[i][2], s[i][3]));
            mx = fmaxf(mx, __shfl_xor_sync(0xffffffffu, mx, 1, 16));
            mx = fmaxf(mx, __shfl_xor_sync(0xffffffffu, mx, 2, 16));
            mx = fmaxf(mx, __shfl_xor_sync(0xffffffffu, mx, 4, 16));
            mx = fmaxf(mx, __shfl_xor_sync(0xffffffffu, mx, 8, 16));
            const float mn = fmaxf(m[i], mx);
            const float corr = __expf(m[i] - mn);
            m[i] = mn;
            float rs = 0.f;
#pragma unroll
            for (int j = 0; j < 4; ++j) {
                s[i][j] = __expf(s[i][j] - mn);
                rs += s[i][j];
            }
            rs += __shfl_xor_sync(0xffffffffu, rs, 1, 16);
            rs += __shfl_xor_sync(0xffffffffu, rs, 2, 16);
            rs += __shfl_xor_sync(0xffffffffu, rs, 4, 16);
            rs += __shfl_xor_sync(0xffffffffu, rs, 8, 16);
            l[i] = l[i] * corr + rs;
#pragma unroll
            for (int d = 0; d < 8; ++d) o[i][d] *= corr;
#pragma unroll
            for (int j = 0; j < 4; ++j)
                Ps[(tx * 4 + j) * 129 + ty * 8 + i] = s[i][j];
        }
        __syncthreads();

#pragma unroll 2
        for (int cc = 0; cc < 64; ++cc) {
            const float4 v0 = Vs[cc * 32 + tx * 2 + 0];
            const float4 v1 = Vs[cc * 32 + tx * 2 + 1];
#pragma unroll
            for (int i = 0; i < 8; ++i) {
                const float p = Ps[cc * 129 + ty * 8 + i];
                o[i][0] += p * v0.x; o[i][1] += p * v0.y;
                o[i][2] += p * v0.z; o[i][3] += p * v0.w;
                o[i][4] += p * v1.x; o[i][5] += p * v1.y;
                o[i][6] += p * v1.z; o[i][7] += p * v1.w;
            }
        }
        __syncthreads();
    }

    // epilogue -> bf16 hi/lo for GEMM2
#pragma unroll
    for (int i = 0; i < 8; ++i) {
        const float inv = 1.f / l[i];
        const int row_g = qt * 128 + ty * 8 + i;
        const size_t base = (size_t)(b * TT + row_g) * CCH + h * HD + tx * 8;
#pragma unroll
        for (int e = 0; e < 8; ++e) {
            bf16 hv, lv;
            split2(o[i][e] * inv, hv, lv);
            g_ahi[base + e] = hv;
            g_alo[base + e] = lv;
        }
    }
}

// ---------------------------------------------------------------------------
extern "C" void kernel_launch(void* const* d_in, const int* in_sizes, int n_in,
                              void* d_out, int out_size)
{
    const float* x    = (const float*)d_in[0];
    const float* cosp = (const float*)d_in[1];
    const float* sinp = (const float*)d_in[2];
    const float* Wq   = (const float*)d_in[3];
    const float* Wk   = (const float*)d_in[4];
    const float* Wv   = (const float*)d_in[5];
    const float* Wo   = (const float*)d_in[6];
    float* out = (float*)d_out;

    const int attn_smem = ATTN_SMEM_FLOATS * 4;
    cudaFuncSetAttribute(attn_kernel,
                         cudaFuncAttributeMaxDynamicSharedMemorySize, attn_smem);

    // 0. split conversions
    split_x_kernel<<<(MTOT * CCH) / 256, 256>>>(x);
    split_wqkv_kernel<<<(NQKV * CCH) / 256, 256>>>(Wq, Wk, Wv);
    split_wo_kernel<<<(CCH * CCH) / 256, 256>>>(Wo);

    // 1. fused QKV projection (tensor cores)
    gemm_tc<0><<<dim3(NQKV / 128, MTOT / 128), 256>>>(nullptr);

    // 2. RoPE
    const int nrope = BB * NH * TT * 64 + BB * NKV * TT * 64;
    rope_kernel<<<(nrope + 255) / 256, 256>>>(cosp, sinp);

    // 3. causal GQA flash attention
    attn_kernel<<<dim3(TT / 128, BB * NH), 256, attn_smem>>>();

    // 4. output projection (tensor cores)
    gemm_tc<1><<<dim3(CCH / 128, MTOT / 128), 256>>>(out);
}

// round 4
// speedup vs baseline: 3.6613x; 2.0976x over previous
#include <cuda_runtime.h>
#include <cuda_bf16.h>
#include <cuda_fp16.h>
#include <cstdint>

#define BB 2
#define TT 2048
#define CCH 2048
#define NH 16
#define NKV 4
#define HD 128
#define MTOT 4096
#define NQKV 3072

typedef __nv_bfloat16 bf16;

// ---- scratch (no cudaMalloc allowed) ----
__device__ bf16 g_xhi[(size_t)MTOT*CCH],  g_xlo[(size_t)MTOT*CCH];
__device__ bf16 g_wqkv_hi[(size_t)NQKV*CCH], g_wqkv_lo[(size_t)NQKV*CCH];
__device__ bf16 g_wo_hi[(size_t)CCH*CCH], g_wo_lo[(size_t)CCH*CCH];
__device__ bf16 g_ahi[(size_t)MTOT*CCH],  g_alo[(size_t)MTOT*CCH];
__device__ float g_q[(size_t)BB*NH*TT*HD];
__device__ float g_k[(size_t)BB*NKV*TT*HD];
__device__ float g_v[(size_t)BB*NKV*TT*HD];
__device__ __half g_qh[(size_t)BB*NH*TT*HD];
__device__ __half g_kh[(size_t)BB*NKV*TT*HD];
__device__ __half g_vh[(size_t)BB*NKV*TT*HD];

__device__ __forceinline__ void split2(float v, bf16& h, bf16& l) {
    h = __float2bfloat16(v);
    l = __float2bfloat16(v - __bfloat162float(h));
}

// ---------------------------------------------------------------------------
// Split / transpose conversion kernels
// ---------------------------------------------------------------------------
__global__ void split_x_kernel(const float* __restrict__ x) {
    const size_t i = (size_t)blockIdx.x * 256 + threadIdx.x;
    split2(x[i], g_xhi[i], g_xlo[i]);
}

__global__ void split_wqkv_kernel(const float* __restrict__ Wq,
                                  const float* __restrict__ Wk,
                                  const float* __restrict__ Wv) {
    const size_t i = (size_t)blockIdx.x * 256 + threadIdx.x;
    const int n = (int)(i >> 11);
    const int k = (int)(i & 2047);
    float v;
    if (n < 2048)      v = Wq[(size_t)k * 2048 + n];
    else if (n < 2560) v = Wk[(size_t)k * 512 + (n - 2048)];
    else               v = Wv[(size_t)k * 512 + (n - 2560)];
    split2(v, g_wqkv_hi[i], g_wqkv_lo[i]);
}

__global__ void split_wo_kernel(const float* __restrict__ Wo) {
    const size_t i = (size_t)blockIdx.x * 256 + threadIdx.x;
    const int n = (int)(i >> 11);
    const int k = (int)(i & 2047);
    split2(Wo[(size_t)k * 2048 + n], g_wo_hi[i], g_wo_lo[i]);
}

// ---------------------------------------------------------------------------
// MMA / ldmatrix helpers
// ---------------------------------------------------------------------------
__device__ __forceinline__ void ldm_x4(unsigned r[4], const void* p) {
    uint32_t a = (uint32_t)__cvta_generic_to_shared(p);
    asm volatile("ldmatrix.sync.aligned.m8n8.x4.shared.b16 {%0,%1,%2,%3}, [%4];"
        : "=r"(r[0]), "=r"(r[1]), "=r"(r[2]), "=r"(r[3]) : "r"(a));
}
__device__ __forceinline__ void ldm_x4_t(unsigned r[4], const void* p) {
    uint32_t a = (uint32_t)__cvta_generic_to_shared(p);
    asm volatile("ldmatrix.sync.aligned.m8n8.x4.trans.shared.b16 {%0,%1,%2,%3}, [%4];"
        : "=r"(r[0]), "=r"(r[1]), "=r"(r[2]), "=r"(r[3]) : "r"(a));
}

__device__ __forceinline__ void mma16816(float c[4],
    unsigned a0, unsigned a1, unsigned a2, unsigned a3, unsigned b0, unsigned b1)
{
    asm volatile(
        "mma.sync.aligned.m16n8k16.row.col.f32.bf16.bf16.f32 "
        "{%0,%1,%2,%3},{%4,%5,%6,%7},{%8,%9},{%0,%1,%2,%3};"
        : "+f"(c[0]), "+f"(c[1]), "+f"(c[2]), "+f"(c[3])
        : "r"(a0), "r"(a1), "r"(a2), "r"(a3), "r"(b0), "r"(b1));
}
__device__ __forceinline__ void mma16816h(float c[4],
    unsigned a0, unsigned a1, unsigned a2, unsigned a3, unsigned b0, unsigned b1)
{
    asm volatile(
        "mma.sync.aligned.m16n8k16.row.col.f32.f16.f16.f32 "
        "{%0,%1,%2,%3},{%4,%5,%6,%7},{%8,%9},{%0,%1,%2,%3};"
        : "+f"(c[0]), "+f"(c[1]), "+f"(c[2]), "+f"(c[3])
        : "r"(a0), "r"(a1), "r"(a2), "r"(a3), "r"(b0), "r"(b1));
}

__device__ __forceinline__ unsigned packf16(float lo, float hi) {
    unsigned d;
    asm("cvt.rn.f16x2.f32 %0, %1, %2;" : "=r"(d) : "f"(hi), "f"(lo));
    return d;
}
__device__ __forceinline__ float ex2(float x) {
    float y; asm("ex2.approx.f32 %0, %1;" : "=f"(y) : "f"(x)); return y;
}

// ---------------------------------------------------------------------------
// Tensor-core split-bf16 GEMM (unchanged from R3)
// ---------------------------------------------------------------------------
#define SPITCH 40

template<int MODE>
__global__ __launch_bounds__(256) void gemm_tc(float* __restrict__ out)
{
    __shared__ bf16 sAh[128 * SPITCH], sAl[128 * SPITCH];
    __shared__ bf16 sBh[128 * SPITCH], sBl[128 * SPITCH];

    const int tid  = threadIdx.x;
    const int lane = tid & 31;
    const int wid  = tid >> 5;
    const int bm = blockIdx.y * 128;
    const int bn = blockIdx.x * 128;
    const int mw = (wid >> 2) * 64;
    const int nw = (wid & 3) * 32;

    const bf16* Ah = (MODE == 0) ? g_xhi : g_ahi;
    const bf16* Al = (MODE == 0) ? g_xlo : g_alo;
    const bf16* Bh = (MODE == 0) ? g_wqkv_hi : g_wo_hi;
    const bf16* Bl = (MODE == 0) ? g_wqkv_lo : g_wo_lo;

    const int lr = tid >> 2;
    const int lq = (tid & 3) * 8;

    float c[4][4][4];
#pragma unroll
    for (int i = 0; i < 4; ++i)
#pragma unroll
        for (int j = 0; j < 4; ++j)
#pragma unroll
            for (int e = 0; e < 4; ++e) c[i][j][e] = 0.f;

    uint4 pAh[2], pAl[2], pBh[2], pBl[2];

#define GLOAD(k0)                                                              \
    do {                                                                       \
        pAh[0] = *(const uint4*)(Ah + (size_t)(bm + lr)      * CCH + (k0) + lq); \
        pAh[1] = *(const uint4*)(Ah + (size_t)(bm + lr + 64) * CCH + (k0) + lq); \
        pAl[0] = *(const uint4*)(Al + (size_t)(bm + lr)      * CCH + (k0) + lq); \
        pAl[1] = *(const uint4*)(Al + (size_t)(bm + lr + 64) * CCH + (k0) + lq); \
        pBh[0] = *(const uint4*)(Bh + (size_t)(bn + lr)      * CCH + (k0) + lq); \
        pBh[1] = *(const uint4*)(Bh + (size_t)(bn + lr + 64) * CCH + (k0) + lq); \
        pBl[0] = *(const uint4*)(Bl + (size_t)(bn + lr)      * CCH + (k0) + lq); \
        pBl[1] = *(const uint4*)(Bl + (size_t)(bn + lr + 64) * CCH + (k0) + lq); \
    } while (0)

#define SSTORE()                                                               \
    do {                                                                       \
        *(uint4*)&sAh[lr * SPITCH + lq]        = pAh[0];                       \
        *(uint4*)&sAh[(lr + 64) * SPITCH + lq] = pAh[1];                       \
        *(uint4*)&sAl[lr * SPITCH + lq]        = pAl[0];                       \
        *(uint4*)&sAl[(lr + 64) * SPITCH + lq] = pAl[1];                       \
        *(uint4*)&sBh[lr * SPITCH + lq]        = pBh[0];                       \
        *(uint4*)&sBh[(lr + 64) * SPITCH + lq] = pBh[1];                       \
        *(uint4*)&sBl[lr * SPITCH + lq]        = pBl[0];                       \
        *(uint4*)&sBl[(lr + 64) * SPITCH + lq] = pBl[1];                       \
    } while (0)

    GLOAD(0);
    SSTORE();
    __syncthreads();

    const int arow = ((lane >> 3) & 1) * 8 + (lane & 7);
    const int acol = (lane >> 4) * 8;
    const int brow = (lane >> 4) * 8 + (lane & 7);
    const int bcol = ((lane >> 3) & 1) * 8;

    const int NKT = CCH / 32;
    for (int kt = 0; kt < NKT; ++kt) {
        if (kt + 1 < NKT) GLOAD((kt + 1) * 32);

#pragma unroll
        for (int kk = 0; kk < 2; ++kk) {
            unsigned ah[4][4], al[4][4], bh[2][4], bl[2][4];
#pragma unroll
            for (int mi = 0; mi < 4; ++mi) {
                const int off = (mw + mi * 16 + arow) * SPITCH + kk * 16 + acol;
                ldm_x4(ah[mi], sAh + off);
                ldm_x4(al[mi], sAl + off);
            }
#pragma unroll
            for (int x = 0; x < 2; ++x) {
                const int off = (nw + x * 16 + brow) * SPITCH + kk * 16 + bcol;
                ldm_x4(bh[x], sBh + off);
                ldm_x4(bl[x], sBl + off);
            }
#pragma unroll
            for (int mi = 0; mi < 4; ++mi) {
#pragma unroll
                for (int nj = 0; nj < 4; ++nj) {
                    const int x = nj >> 1, y = (nj & 1) * 2;
                    mma16816(c[mi][nj], ah[mi][0], ah[mi][1], ah[mi][2], ah[mi][3],
                             bh[x][y], bh[x][y + 1]);
                    mma16816(c[mi][nj], ah[mi][0], ah[mi][1], ah[mi][2], ah[mi][3],
                             bl[x][y], bl[x][y + 1]);
                    mma16816(c[mi][nj], al[mi][0], al[mi][1], al[mi][2], al[mi][3],
                             bh[x][y], bh[x][y + 1]);
                }
            }
        }

        if (kt + 1 < NKT) {
            __syncthreads();
            SSTORE();
            __syncthreads();
        }
    }

#pragma unroll
    for (int mi = 0; mi < 4; ++mi) {
#pragma unroll
        for (int nj = 0; nj < 4; ++nj) {
            const int m = bm + mw + mi * 16 + (lane >> 2);
            const int n = bn + nw + nj * 8 + 2 * (lane & 3);
            const float2 v0 = make_float2(c[mi][nj][0], c[mi][nj][1]);
            const float2 v1 = make_float2(c[mi][nj][2], c[mi][nj][3]);
            if (MODE == 1) {
                *(float2*)(out + (size_t)m * 2048 + n)       = v0;
                *(float2*)(out + (size_t)(m + 8) * 2048 + n) = v1;
            } else {
                const int b = m >> 11, t = m & 2047;
                const int d = n & 127;
                float* dst;
                if (n < 2048) {
                    const int h = n >> 7;
                    dst = g_q + ((size_t)(b * NH + h) * TT + t) * HD + d;
                } else if (n < 2560) {
                    const int kvh = (n - 2048) >> 7;
                    dst = g_k + ((size_t)(b * NKV + kvh) * TT + t) * HD + d;
                } else {
                    const int kvh = (n - 2560) >> 7;
                    dst = g_v + ((size_t)(b * NKV + kvh) * TT + t) * HD + d;
                }
                *(float2*)dst = v0;
                *(float2*)(dst + 8 * HD) = v1;
            }
        }
    }
}

// ---------------------------------------------------------------------------
// RoPE + fp16 conversion: q (scaled by 1/sqrt(HD)*log2e), k, v -> fp16
// ---------------------------------------------------------------------------
__global__ void rope_cvt_kernel(const float* __restrict__ cosp,
                                const float* __restrict__ sinp)
{
    const int i = blockIdx.x * 256 + threadIdx.x;
    const int nq = 1 << 22;          // BB*NH*TT*64
    const int nk = 1 << 20;          // BB*NKV*TT*64
    const int nv = 1 << 20;

    if (i < nq) {
        const int d = i & 63, t = (i >> 6) & 2047, bh = i >> 17;
        const float* src = g_q + ((size_t)bh * TT + t) * HD;
        __half* dst = g_qh + ((size_t)bh * TT + t) * HD;
        const float SC = 0.08838834764831845f * 1.44269504088896341f;
        const float c0 = cosp[t * HD + d],      s0 = sinp[t * HD + d];
        const float c1 = cosp[t * HD + d + 64], s1 = sinp[t * HD + d + 64];
        const float x0 = src[d], x1 = src[d + 64];
        dst[d]      = __float2half((x0 * c0 - x1 * s0) * SC);
        dst[d + 64] = __float2half((x1 * c1 + x0 * s1) * SC);
    } else if (i < nq + nk) {
        const int i2 = i - nq;
        const int d = i2 & 63, t = (i2 >> 6) & 2047, bkv = i2 >> 17;
        const float* src = g_k + ((size_t)bkv * TT + t) * HD;
        __half* dst = g_kh + ((size_t)bkv * TT + t) * HD;
        const float c0 = cosp[t * HD + d],      s0 = sinp[t * HD + d];
        const float c1 = cosp[t * HD + d + 64], s1 = sinp[t * HD + d + 64];
        const float x0 = src[d], x1 = src[d + 64];
        dst[d]      = __float2half(x0 * c0 - x1 * s0);
        dst[d + 64] = __float2half(x1 * c1 + x0 * s1);
    } else if (i < nq + nk + nv) {
        const int i3 = i - nq - nk;
        const int d = i3 & 63, t = (i3 >> 6) & 2047, bkv = i3 >> 17;
        const float* src = g_v + ((size_t)bkv * TT + t) * HD;
        __half* dst = g_vh + ((size_t)bkv * TT + t) * HD;
        dst[d]      = __float2half(src[d]);
        dst[d + 64] = __float2half(src[d + 64]);
    }
}

// ---------------------------------------------------------------------------
// Tensor-core flash attention, fp16 inputs, fp32 accum.
// CTA: 256 thr (8 warps), 128 q-rows, 64-key tiles. Warp w: rows w*16..+15.
// smem pitch 136 halves (272B) -> conflict-free ldmatrix.
// ---------------------------------------------------------------------------
#define APITCH 136
#define ATT_SMEM_BYTES ((128 + 64 + 64) * APITCH * 2)

__global__ __launch_bounds__(256, 1) void attn_tc()
{
    extern __shared__ __half sh2[];
    __half* sQ = sh2;
    __half* sK = sh2 + 128 * APITCH;
    __half* sV = sh2 + 192 * APITCH;

    const int tid = threadIdx.x;
    const int wid = tid >> 5, lane = tid & 31;
    const int r = lane >> 2, cq = lane & 3;
    const int qt = (int)gridDim.x - 1 - (int)blockIdx.x;   // heavy first
    const int bh = blockIdx.y;
    const int b = bh >> 4, h = bh & 15, kvh = h >> 2;

    const uint4* qg = (const uint4*)(g_qh + (size_t)bh * TT * HD + (size_t)qt * 128 * HD);
    const uint4* kg = (const uint4*)(g_kh + (size_t)(b * NKV + kvh) * TT * HD);
    const uint4* vg = (const uint4*)(g_vh + (size_t)(b * NKV + kvh) * TT * HD);

    // Q tile -> smem (coalesced)
#pragma unroll
    for (int it = 0; it < 8; ++it) {
        const int idx = it * 256 + tid;
        *(uint4*)&sQ[(idx >> 4) * APITCH + (idx & 15) * 8] = qg[idx];
    }
    __syncthreads();

    // cache Q fragments (invariant across key tiles)
    unsigned qf[8][4];
    {
        const int arow = wid * 16 + (lane & 15);
        const int acol = (lane >> 4) * 8;
#pragma unroll
        for (int kk = 0; kk < 8; ++kk)
            ldm_x4(qf[kk], sQ + arow * APITCH + kk * 16 + acol);
    }

    float o[16][4];
#pragma unroll
    for (int nj = 0; nj < 16; ++nj)
#pragma unroll
        for (int e = 0; e < 4; ++e) o[nj][e] = 0.f;
    float m0 = -1e30f, m1 = -1e30f, l0 = 0.f, l1 = 0.f;

    const int krow = (lane & 7) + ((lane >> 4) << 3);
    const int kcol = ((lane >> 3) & 1) * 8;
    const int vrow = lane & 15;
    const int vcol = (lane >> 4) * 8;

    const int ntiles = 2 * qt + 2;
    for (int kt = 0; kt < ntiles; ++kt) {
        // K/V tiles -> smem
#pragma unroll
        for (int it = 0; it < 4; ++it) {
            const int idx = it * 256 + tid;
            const int row = idx >> 4, q8 = (idx & 15) * 8;
            *(uint4*)&sK[row * APITCH + q8] = kg[(size_t)kt * 1024 + idx];
            *(uint4*)&sV[row * APITCH + q8] = vg[(size_t)kt * 1024 + idx];
        }
        __syncthreads();

        // S = Q K^T
        float s[8][4];
#pragma unroll
        for (int nj = 0; nj < 8; ++nj)
#pragma unroll
            for (int e = 0; e < 4; ++e) s[nj][e] = 0.f;

#pragma unroll
        for (int kk = 0; kk < 8; ++kk) {
#pragma unroll
            for (int nb = 0; nb < 4; ++nb) {
                unsigned kf[4];
                ldm_x4(kf, sK + (nb * 16 + krow) * APITCH + kk * 16 + kcol);
                mma16816h(s[nb * 2],     qf[kk][0], qf[kk][1], qf[kk][2], qf[kk][3], kf[0], kf[1]);
                mma16816h(s[nb * 2 + 1], qf[kk][0], qf[kk][1], qf[kk][2], qf[kk][3], kf[2], kf[3]);
            }
        }

        // causal mask (diagonal tiles only)
        if (kt >= 2 * qt) {
            const int row0 = qt * 128 + wid * 16 + r;
#pragma unroll
            for (int nj = 0; nj < 8; ++nj) {
                const int key = kt * 64 + nj * 8 + 2 * cq;
                if (key > row0)         s[nj][0] = -1e30f;
                if (key + 1 > row0)     s[nj][1] = -1e30f;
                if (key > row0 + 8)     s[nj][2] = -1e30f;
                if (key + 1 > row0 + 8) s[nj][3] = -1e30f;
            }
        }

        // online softmax (exp2 domain; log2e folded into Q scale)
        float mx0 = s[0][0], mx1 = s[0][2];
#pragma unroll
        for (int nj = 0; nj < 8; ++nj) {
            mx0 = fmaxf(mx0, fmaxf(s[nj][0], s[nj][1]));
            mx1 = fmaxf(mx1, fmaxf(s[nj][2], s[nj][3]));
        }
        mx0 = fmaxf(mx0, __shfl_xor_sync(0xffffffffu, mx0, 1));
        mx0 = fmaxf(mx0, __shfl_xor_sync(0xffffffffu, mx0, 2));
        mx1 = fmaxf(mx1, __shfl_xor_sync(0xffffffffu, mx1, 1));
        mx1 = fmaxf(mx1, __shfl_xor_sync(0xffffffffu, mx1, 2));

        const float mn0 = fmaxf(m0, mx0), mn1 = fmaxf(m1, mx1);
        const float cr0 = ex2(m0 - mn0),  cr1 = ex2(m1 - mn1);
        m0 = mn0; m1 = mn1;

        float sum0 = 0.f, sum1 = 0.f;
#pragma unroll
        for (int nj = 0; nj < 8; ++nj) {
            s[nj][0] = ex2(s[nj][0] - mn0); sum0 += s[nj][0];
            s[nj][1] = ex2(s[nj][1] - mn0); sum0 += s[nj][1];
            s[nj][2] = ex2(s[nj][2] - mn1); sum1 += s[nj][2];
            s[nj][3] = ex2(s[nj][3] - mn1); sum1 += s[nj][3];
        }
        sum0 += __shfl_xor_sync(0xffffffffu, sum0, 1);
        sum0 += __shfl_xor_sync(0xffffffffu, sum0, 2);
        sum1 += __shfl_xor_sync(0xffffffffu, sum1, 1);
        sum1 += __shfl_xor_sync(0xffffffffu, sum1, 2);
        l0 = l0 * cr0 + sum0;
        l1 = l1 * cr1 + sum1;

#pragma unroll
        for (int nj = 0; nj < 16; ++nj) {
            o[nj][0] *= cr0; o[nj][1] *= cr0;
            o[nj][2] *= cr1; o[nj][3] *= cr1;
        }

        // pack P into PV A-fragments (register-resident)
        unsigned p[8][2];
#pragma unroll
        for (int nj = 0; nj < 8; ++nj) {
            p[nj][0] = packf16(s[nj][0], s[nj][1]);
            p[nj][1] = packf16(s[nj][2], s[nj][3]);
        }

        // O += P V
#pragma unroll
        for (int kk = 0; kk < 4; ++kk) {
            const unsigned a0 = p[2 * kk][0],     a1 = p[2 * kk][1];
            const unsigned a2 = p[2 * kk + 1][0], a3 = p[2 * kk + 1][1];
#pragma unroll
            for (int db = 0; db < 8; ++db) {
                unsigned vf[4];
                ldm_x4_t(vf, sV + (kk * 16 + vrow) * APITCH + db * 16 + vcol);
                mma16816h(o[db * 2],     a0, a1, a2, a3, vf[0], vf[1]);
                mma16816h(o[db * 2 + 1], a0, a1, a2, a3, vf[2], vf[3]);
            }
        }
        __syncthreads();
    }

    // epilogue -> split bf16 for GEMM2
    const float inv0 = 1.f / l0, inv1 = 1.f / l1;
    const int row0 = qt * 128 + wid * 16 + r;
    const size_t base0 = ((size_t)(b * TT + row0)) * CCH + h * HD;
    const size_t base1 = base0 + 8 * CCH;
#pragma unroll
    for (int nj = 0; nj < 16; ++nj) {
        const int d = nj * 8 + 2 * cq;
        bf16 hv, lv;
        split2(o[nj][0] * inv0, hv, lv); g_ahi[base0 + d]     = hv; g_alo[base0 + d]     = lv;
        split2(o[nj][1] * inv0, hv, lv); g_ahi[base0 + d + 1] = hv; g_alo[base0 + d + 1] = lv;
        split2(o[nj][2] * inv1, hv, lv); g_ahi[base1 + d]     = hv; g_alo[base1 + d]     = lv;
        split2(o[nj][3] * inv1, hv, lv); g_ahi[base1 + d + 1] = hv; g_alo[base1 + d + 1] = lv;
    }
}

// ---------------------------------------------------------------------------
extern "C" void kernel_launch(void* const* d_in, const int* in_sizes, int n_in,
                              void* d_out, int out_size)
{
    const float* x    = (const float*)d_in[0];
    const float* cosp = (const float*)d_in[1];
    const float* sinp = (const float*)d_in[2];
    const float* Wq   = (const float*)d_in[3];
    const float* Wk   = (const float*)d_in[4];
    const float* Wv   = (const float*)d_in[5];
    const float* Wo   = (const float*)d_in[6];
    float* out = (float*)d_out;

    cudaFuncSetAttribute(attn_tc,
                         cudaFuncAttributeMaxDynamicSharedMemorySize, ATT_SMEM_BYTES);

    // 0. split conversions
    split_x_kernel<<<(MTOT * CCH) / 256, 256>>>(x);
    split_wqkv_kernel<<<(NQKV * CCH) / 256, 256>>>(Wq, Wk, Wv);
    split_wo_kernel<<<(CCH * CCH) / 256, 256>>>(Wo);

    // 1. fused QKV projection (tensor cores, split bf16)
    gemm_tc<0><<<dim3(NQKV / 128, MTOT / 128), 256>>>(nullptr);

    // 2. RoPE + fp16 conversion
    rope_cvt_kernel<<<24576, 256>>>(cosp, sinp);

    // 3. tensor-core causal GQA flash attention
    attn_tc<<<dim3(TT / 128, BB * NH), 256, ATT_SMEM_BYTES>>>();

    // 4. output projection (tensor cores, split bf16)
    gemm_tc<1><<<dim3(CCH / 128, MTOT / 128), 256>>>(out);
}

// round 5
// speedup vs baseline: 4.4292x; 1.2097x over previous
#include <cuda_runtime.h>
#include <cuda_bf16.h>
#include <cuda_fp16.h>
#include <cstdint>

#define BB 2
#define TT 2048
#define CCH 2048
#define NH 16
#define NKV 4
#define HD 128
#define MTOT 4096
#define NQKV 3072

typedef __nv_bfloat16 bf16;

// ---- scratch (no cudaMalloc allowed) ----
__device__ bf16 g_xhi[(size_t)MTOT*CCH],  g_xlo[(size_t)MTOT*CCH];
__device__ bf16 g_wqkv_hi[(size_t)NQKV*CCH], g_wqkv_lo[(size_t)NQKV*CCH];
__device__ bf16 g_wo_hi[(size_t)CCH*CCH], g_wo_lo[(size_t)CCH*CCH];
__device__ bf16 g_ahi[(size_t)MTOT*CCH],  g_alo[(size_t)MTOT*CCH];
__device__ float g_q[(size_t)BB*NH*TT*HD];
__device__ float g_k[(size_t)BB*NKV*TT*HD];
__device__ float g_v[(size_t)BB*NKV*TT*HD];
__device__ __half g_qh[(size_t)BB*NH*TT*HD];
__device__ __half g_kh[(size_t)BB*NKV*TT*HD];
__device__ __half g_vh[(size_t)BB*NKV*TT*HD];

__device__ __forceinline__ void split2(float v, bf16& h, bf16& l) {
    h = __float2bfloat16(v);
    l = __float2bfloat16(v - __bfloat162float(h));
}

// ---------------------------------------------------------------------------
// Conversion kernels
// ---------------------------------------------------------------------------
__global__ void split_x_kernel(const float* __restrict__ x) {
    const size_t i = (size_t)blockIdx.x * 256 + threadIdx.x;
    split2(x[i], g_xhi[i], g_xlo[i]);
}

// tiled transpose-split: W[k][n] -> hi/lo[n][k], coalesced both sides
__global__ void tsplit_wqkv(const float* __restrict__ Wq,
                            const float* __restrict__ Wk,
                            const float* __restrict__ Wv) {
    __shared__ float tile[32][33];
    const int n0 = blockIdx.x * 32, k0 = blockIdx.y * 32;
    const int tx = threadIdx.x & 31, ty = threadIdx.x >> 5;
#pragma unroll
    for (int p = 0; p < 4; ++p) {
        const int r = ty + p * 8;
        const int n = n0 + tx;
        float v;
        if (n0 < 2048)      v = Wq[(size_t)(k0 + r) * 2048 + n];
        else if (n0 < 2560) v = Wk[(size_t)(k0 + r) * 512 + (n - 2048)];
        else                v = Wv[(size_t)(k0 + r) * 512 + (n - 2560)];
        tile[r][tx] = v;
    }
    __syncthreads();
#pragma unroll
    for (int p = 0; p < 4; ++p) {
        const int a = ty + p * 8;
        bf16 h, l; split2(tile[tx][a], h, l);
        const size_t o = (size_t)(n0 + a) * 2048 + k0 + tx;
        g_wqkv_hi[o] = h; g_wqkv_lo[o] = l;
    }
}

__global__ void tsplit_wo(const float* __restrict__ Wo) {
    __shared__ float tile[32][33];
    const int n0 = blockIdx.x * 32, k0 = blockIdx.y * 32;
    const int tx = threadIdx.x & 31, ty = threadIdx.x >> 5;
#pragma unroll
    for (int p = 0; p < 4; ++p) {
        const int r = ty + p * 8;
        tile[r][tx] = Wo[(size_t)(k0 + r) * 2048 + n0 + tx];
    }
    __syncthreads();
#pragma unroll
    for (int p = 0; p < 4; ++p) {
        const int a = ty + p * 8;
        bf16 h, l; split2(tile[tx][a], h, l);
        const size_t o = (size_t)(n0 + a) * 2048 + k0 + tx;
        g_wo_hi[o] = h; g_wo_lo[o] = l;
    }
}

// ---------------------------------------------------------------------------
// MMA / ldmatrix / cp.async helpers
// ---------------------------------------------------------------------------
__device__ __forceinline__ void ldm_x4(unsigned r[4], const void* p) {
    uint32_t a = (uint32_t)__cvta_generic_to_shared(p);
    asm volatile("ldmatrix.sync.aligned.m8n8.x4.shared.b16 {%0,%1,%2,%3}, [%4];"
        : "=r"(r[0]), "=r"(r[1]), "=r"(r[2]), "=r"(r[3]) : "r"(a));
}
__device__ __forceinline__ void ldm_x4_t(unsigned r[4], const void* p) {
    uint32_t a = (uint32_t)__cvta_generic_to_shared(p);
    asm volatile("ldmatrix.sync.aligned.m8n8.x4.trans.shared.b16 {%0,%1,%2,%3}, [%4];"
        : "=r"(r[0]), "=r"(r[1]), "=r"(r[2]), "=r"(r[3]) : "r"(a));
}
__device__ __forceinline__ void mma16816(float c[4],
    unsigned a0, unsigned a1, unsigned a2, unsigned a3, unsigned b0, unsigned b1)
{
    asm volatile(
        "mma.sync.aligned.m16n8k16.row.col.f32.bf16.bf16.f32 "
        "{%0,%1,%2,%3},{%4,%5,%6,%7},{%8,%9},{%0,%1,%2,%3};"
        : "+f"(c[0]), "+f"(c[1]), "+f"(c[2]), "+f"(c[3])
        : "r"(a0), "r"(a1), "r"(a2), "r"(a3), "r"(b0), "r"(b1));
}
__device__ __forceinline__ void mma16816h(float c[4],
    unsigned a0, unsigned a1, unsigned a2, unsigned a3, unsigned b0, unsigned b1)
{
    asm volatile(
        "mma.sync.aligned.m16n8k16.row.col.f32.f16.f16.f32 "
        "{%0,%1,%2,%3},{%4,%5,%6,%7},{%8,%9},{%0,%1,%2,%3};"
        : "+f"(c[0]), "+f"(c[1]), "+f"(c[2]), "+f"(c[3])
        : "r"(a0), "r"(a1), "r"(a2), "r"(a3), "r"(b0), "r"(b1));
}
__device__ __forceinline__ unsigned packf16(float lo, float hi) {
    unsigned d;
    asm("cvt.rn.f16x2.f32 %0, %1, %2;" : "=r"(d) : "f"(hi), "f"(lo));
    return d;
}
__device__ __forceinline__ float ex2(float x) {
    float y; asm("ex2.approx.f32 %0, %1;" : "=f"(y) : "f"(x)); return y;
}
__device__ __forceinline__ void cpasync16(void* smem, const void* gmem) {
    uint32_t s = (uint32_t)__cvta_generic_to_shared(smem);
    asm volatile("cp.async.cg.shared.global [%0], [%1], 16;" :: "r"(s), "l"(gmem));
}
#define CP_COMMIT() asm volatile("cp.async.commit_group;")
template<int N> __device__ __forceinline__ void cp_wait() {
    asm volatile("cp.async.wait_group %0;" :: "n"(N));
}

// ---------------------------------------------------------------------------
// Tensor-core split-bf16 GEMM, cp.async double-buffered, 2 CTAs/SM.
// 128x128 tile, BK=32, 256 threads (8 warps 2x4), 3-term split MMA.
// ---------------------------------------------------------------------------
#define SPITCH 40
#define STAGE_HALVES (128 * SPITCH)
#define GEMM_SMEM_BYTES (8 * STAGE_HALVES * 2)   // 4 arrays x 2 stages

template<int MODE>
__global__ __launch_bounds__(256, 2) void gemm_tc(float* __restrict__ out)
{
    extern __shared__ bf16 dsm[];
    bf16* sAh = dsm;
    bf16* sAl = dsm + 2 * STAGE_HALVES;
    bf16* sBh = dsm + 4 * STAGE_HALVES;
    bf16* sBl = dsm + 6 * STAGE_HALVES;

    const int tid  = threadIdx.x;
    const int lane = tid & 31;
    const int wid  = tid >> 5;
    const int bm = blockIdx.y * 128;
    const int bn = blockIdx.x * 128;
    const int mw = (wid >> 2) * 64;
    const int nw = (wid & 3) * 32;

    const bf16* Ah = (MODE == 0) ? g_xhi : g_ahi;
    const bf16* Al = (MODE == 0) ? g_xlo : g_alo;
    const bf16* Bh = (MODE == 0) ? g_wqkv_hi : g_wo_hi;
    const bf16* Bl = (MODE == 0) ? g_wqkv_lo : g_wo_lo;

    const int lr = tid >> 2;
    const int lq = (tid & 3) * 8;
    const int so0 = lr * SPITCH + lq;
    const int so1 = (lr + 64) * SPITCH + lq;

    const bf16* gA0h = Ah + (size_t)(bm + lr) * CCH + lq;
    const bf16* gA1h = Ah + (size_t)(bm + lr + 64) * CCH + lq;
    const bf16* gA0l = Al + (size_t)(bm + lr) * CCH + lq;
    const bf16* gA1l = Al + (size_t)(bm + lr + 64) * CCH + lq;
    const bf16* gB0h = Bh + (size_t)(bn + lr) * CCH + lq;
    const bf16* gB1h = Bh + (size_t)(bn + lr + 64) * CCH + lq;
    const bf16* gB0l = Bl + (size_t)(bn + lr) * CCH + lq;
    const bf16* gB1l = Bl + (size_t)(bn + lr + 64) * CCH + lq;

#define ISSUE(kt)                                                              \
    do {                                                                       \
        const int _k0 = (kt) * 32;                                             \
        const int _bo = ((kt) & 1) * STAGE_HALVES;                             \
        cpasync16(sAh + _bo + so0, gA0h + _k0);                                \
        cpasync16(sAh + _bo + so1, gA1h + _k0);                                \
        cpasync16(sAl + _bo + so0, gA0l + _k0);                                \
        cpasync16(sAl + _bo + so1, gA1l + _k0);                                \
        cpasync16(sBh + _bo + so0, gB0h + _k0);                                \
        cpasync16(sBh + _bo + so1, gB1h + _k0);                                \
        cpasync16(sBl + _bo + so0, gB0l + _k0);                                \
        cpasync16(sBl + _bo + so1, gB1l + _k0);                                \
        CP_COMMIT();                                                           \
    } while (0)

    float c[4][4][4];
#pragma unroll
    for (int i = 0; i < 4; ++i)
#pragma unroll
        for (int j = 0; j < 4; ++j)
#pragma unroll
            for (int e = 0; e < 4; ++e) c[i][j][e] = 0.f;

    ISSUE(0);

    const int arow = ((lane >> 3) & 1) * 8 + (lane & 7);
    const int acol = (lane >> 4) * 8;
    const int brow = (lane >> 4) * 8 + (lane & 7);
    const int bcol = ((lane >> 3) & 1) * 8;

    const int NKT = CCH / 32;
    for (int kt = 0; kt < NKT; ++kt) {
        cp_wait<0>();
        __syncthreads();
        if (kt + 1 < NKT) ISSUE(kt + 1);

        const int bo = (kt & 1) * STAGE_HALVES;
#pragma unroll
        for (int kk = 0; kk < 2; ++kk) {
            unsigned ah[4][4], al[4][4], bh[2][4], bl[2][4];
#pragma unroll
            for (int mi = 0; mi < 4; ++mi) {
                const int off = bo + (mw + mi * 16 + arow) * SPITCH + kk * 16 + acol;
                ldm_x4(ah[mi], sAh + off);
                ldm_x4(al[mi], sAl + off);
            }
#pragma unroll
            for (int x = 0; x < 2; ++x) {
                const int off = bo + (nw + x * 16 + brow) * SPITCH + kk * 16 + bcol;
                ldm_x4(bh[x], sBh + off);
                ldm_x4(bl[x], sBl + off);
            }
#pragma unroll
            for (int mi = 0; mi < 4; ++mi) {
#pragma unroll
                for (int nj = 0; nj < 4; ++nj) {
                    const int x = nj >> 1, y = (nj & 1) * 2;
                    mma16816(c[mi][nj], ah[mi][0], ah[mi][1], ah[mi][2], ah[mi][3],
                             bh[x][y], bh[x][y + 1]);
                    mma16816(c[mi][nj], ah[mi][0], ah[mi][1], ah[mi][2], ah[mi][3],
                             bl[x][y], bl[x][y + 1]);
                    mma16816(c[mi][nj], al[mi][0], al[mi][1], al[mi][2], al[mi][3],
                             bh[x][y], bh[x][y + 1]);
                }
            }
        }
        __syncthreads();
    }

#pragma unroll
    for (int mi = 0; mi < 4; ++mi) {
#pragma unroll
        for (int nj = 0; nj < 4; ++nj) {
            const int m = bm + mw + mi * 16 + (lane >> 2);
            const int n = bn + nw + nj * 8 + 2 * (lane & 3);
            const float2 v0 = make_float2(c[mi][nj][0], c[mi][nj][1]);
            const float2 v1 = make_float2(c[mi][nj][2], c[mi][nj][3]);
            if (MODE == 1) {
                *(float2*)(out + (size_t)m * 2048 + n)       = v0;
                *(float2*)(out + (size_t)(m + 8) * 2048 + n) = v1;
            } else {
                const int b = m >> 11, t = m & 2047;
                const int d = n & 127;
                float* dst;
                if (n < 2048) {
                    const int h = n >> 7;
                    dst = g_q + ((size_t)(b * NH + h) * TT + t) * HD + d;
                } else if (n < 2560) {
                    const int kvh = (n - 2048) >> 7;
                    dst = g_k + ((size_t)(b * NKV + kvh) * TT + t) * HD + d;
                } else {
                    const int kvh = (n - 2560) >> 7;
                    dst = g_v + ((size_t)(b * NKV + kvh) * TT + t) * HD + d;
                }
                *(float2*)dst = v0;
                *(float2*)(dst + 8 * HD) = v1;
            }
        }
    }
}

// ---------------------------------------------------------------------------
// RoPE + fp16 conversion (q pre-scaled by 1/sqrt(HD)*log2e)
// ---------------------------------------------------------------------------
__global__ void rope_cvt_kernel(const float* __restrict__ cosp,
                                const float* __restrict__ sinp)
{
    const int i = blockIdx.x * 256 + threadIdx.x;
    const int nq = 1 << 22;
    const int nk = 1 << 20;
    const int nv = 1 << 20;

    if (i < nq) {
        const int d = i & 63, t = (i >> 6) & 2047, bh = i >> 17;
        const float* src = g_q + ((size_t)bh * TT + t) * HD;
        __half* dst = g_qh + ((size_t)bh * TT + t) * HD;
        const float SC = 0.08838834764831845f * 1.44269504088896341f;
        const float c0 = cosp[t * HD + d],      s0 = sinp[t * HD + d];
        const float c1 = cosp[t * HD + d + 64], s1 = sinp[t * HD + d + 64];
        const float x0 = src[d], x1 = src[d + 64];
        dst[d]      = __float2half((x0 * c0 - x1 * s0) * SC);
        dst[d + 64] = __float2half((x1 * c1 + x0 * s1) * SC);
    } else if (i < nq + nk) {
        const int i2 = i - nq;
        const int d = i2 & 63, t = (i2 >> 6) & 2047, bkv = i2 >> 17;
        const float* src = g_k + ((size_t)bkv * TT + t) * HD;
        __half* dst = g_kh + ((size_t)bkv * TT + t) * HD;
        const float c0 = cosp[t * HD + d],      s0 = sinp[t * HD + d];
        const float c1 = cosp[t * HD + d + 64], s1 = sinp[t * HD + d + 64];
        const float x0 = src[d], x1 = src[d + 64];
        dst[d]      = __float2half(x0 * c0 - x1 * s0);
        dst[d + 64] = __float2half(x1 * c1 + x0 * s1);
    } else if (i < nq + nk + nv) {
        const int i3 = i - nq - nk;
        const int d = i3 & 63, t = (i3 >> 6) & 2047, bkv = i3 >> 17;
        const float* src = g_v + ((size_t)bkv * TT + t) * HD;
        __half* dst = g_vh + ((size_t)bkv * TT + t) * HD;
        dst[d]      = __float2half(src[d]);
        dst[d + 64] = __float2half(src[d + 64]);
    }
}

// ---------------------------------------------------------------------------
// Tensor-core flash attention (unchanged from R4)
// ---------------------------------------------------------------------------
#define APITCH 136
#define ATT_SMEM_BYTES ((128 + 64 + 64) * APITCH * 2)

__global__ __launch_bounds__(256, 1) void attn_tc()
{
    extern __shared__ __half sh2[];
    __half* sQ = sh2;
    __half* sK = sh2 + 128 * APITCH;
    __half* sV = sh2 + 192 * APITCH;

    const int tid = threadIdx.x;
    const int wid = tid >> 5, lane = tid & 31;
    const int r = lane >> 2, cq = lane & 3;
    const int qt = (int)gridDim.x - 1 - (int)blockIdx.x;
    const int bh = blockIdx.y;
    const int b = bh >> 4, h = bh & 15, kvh = h >> 2;

    const uint4* qg = (const uint4*)(g_qh + (size_t)bh * TT * HD + (size_t)qt * 128 * HD);
    const uint4* kg = (const uint4*)(g_kh + (size_t)(b * NKV + kvh) * TT * HD);
    const uint4* vg = (const uint4*)(g_vh + (size_t)(b * NKV + kvh) * TT * HD);

#pragma unroll
    for (int it = 0; it < 8; ++it) {
        const int idx = it * 256 + tid;
        *(uint4*)&sQ[(idx >> 4) * APITCH + (idx & 15) * 8] = qg[idx];
    }
    __syncthreads();

    unsigned qf[8][4];
    {
        const int arow = wid * 16 + (lane & 15);
        const int acol = (lane >> 4) * 8;
#pragma unroll
        for (int kk = 0; kk < 8; ++kk)
            ldm_x4(qf[kk], sQ + arow * APITCH + kk * 16 + acol);
    }

    float o[16][4];
#pragma unroll
    for (int nj = 0; nj < 16; ++nj)
#pragma unroll
        for (int e = 0; e < 4; ++e) o[nj][e] = 0.f;
    float m0 = -1e30f, m1 = -1e30f, l0 = 0.f, l1 = 0.f;

    const int krow = (lane & 7) + ((lane >> 4) << 3);
    const int kcol = ((lane >> 3) & 1) * 8;
    const int vrow = lane & 15;
    const int vcol = (lane >> 4) * 8;

    const int ntiles = 2 * qt + 2;
    for (int kt = 0; kt < ntiles; ++kt) {
#pragma unroll
        for (int it = 0; it < 4; ++it) {
            const int idx = it * 256 + tid;
            const int row = idx >> 4, q8 = (idx & 15) * 8;
            *(uint4*)&sK[row * APITCH + q8] = kg[(size_t)kt * 1024 + idx];
            *(uint4*)&sV[row * APITCH + q8] = vg[(size_t)kt * 1024 + idx];
        }
        __syncthreads();

        float s[8][4];
#pragma unroll
        for (int nj = 0; nj < 8; ++nj)
#pragma unroll
            for (int e = 0; e < 4; ++e) s[nj][e] = 0.f;

#pragma unroll
        for (int kk = 0; kk < 8; ++kk) {
#pragma unroll
            for (int nb = 0; nb < 4; ++nb) {
                unsigned kf[4];
                ldm_x4(kf, sK + (nb * 16 + krow) * APITCH + kk * 16 + kcol);
                mma16816h(s[nb * 2],     qf[kk][0], qf[kk][1], qf[kk][2], qf[kk][3], kf[0], kf[1]);
                mma16816h(s[nb * 2 + 1], qf[kk][0], qf[kk][1], qf[kk][2], qf[kk][3], kf[2], kf[3]);
            }
        }

        if (kt >= 2 * qt) {
            const int row0 = qt * 128 + wid * 16 + r;
#pragma unroll
            for (int nj = 0; nj < 8; ++nj) {
                const int key = kt * 64 + nj * 8 + 2 * cq;
                if (key > row0)         s[nj][0] = -1e30f;
                if (key + 1 > row0)     s[nj][1] = -1e30f;
                if (key > row0 + 8)     s[nj][2] = -1e30f;
                if (key + 1 > row0 + 8) s[nj][3] = -1e30f;
            }
        }

        float mx0 = s[0][0], mx1 = s[0][2];
#pragma unroll
        for (int nj = 0; nj < 8; ++nj) {
            mx0 = fmaxf(mx0, fmaxf(s[nj][0], s[nj][1]));
            mx1 = fmaxf(mx1, fmaxf(s[nj][2], s[nj][3]));
        }
        mx0 = fmaxf(mx0, __shfl_xor_sync(0xffffffffu, mx0, 1));
        mx0 = fmaxf(mx0, __shfl_xor_sync(0xffffffffu, mx0, 2));
        mx1 = fmaxf(mx1, __shfl_xor_sync(0xffffffffu, mx1, 1));
        mx1 = fmaxf(mx1, __shfl_xor_sync(0xffffffffu, mx1, 2));

        const float mn0 = fmaxf(m0, mx0), mn1 = fmaxf(m1, mx1);
        const float cr0 = ex2(m0 - mn0),  cr1 = ex2(m1 - mn1);
        m0 = mn0; m1 = mn1;

        float sum0 = 0.f, sum1 = 0.f;
#pragma unroll
        for (int nj = 0; nj < 8; ++nj) {
            s[nj][0] = ex2(s[nj][0] - mn0); sum0 += s[nj][0];
            s[nj][1] = ex2(s[nj][1] - mn0); sum0 += s[nj][1];
            s[nj][2] = ex2(s[nj][2] - mn1); sum1 += s[nj][2];
            s[nj][3] = ex2(s[nj][3] - mn1); sum1 += s[nj][3];
        }
        sum0 += __shfl_xor_sync(0xffffffffu, sum0, 1);
        sum0 += __shfl_xor_sync(0xffffffffu, sum0, 2);
        sum1 += __shfl_xor_sync(0xffffffffu, sum1, 1);
        sum1 += __shfl_xor_sync(0xffffffffu, sum1, 2);
        l0 = l0 * cr0 + sum0;
        l1 = l1 * cr1 + sum1;

#pragma unroll
        for (int nj = 0; nj < 16; ++nj) {
            o[nj][0] *= cr0; o[nj][1] *= cr0;
            o[nj][2] *= cr1; o[nj][3] *= cr1;
        }

        unsigned p[8][2];
#pragma unroll
        for (int nj = 0; nj < 8; ++nj) {
            p[nj][0] = packf16(s[nj][0], s[nj][1]);
            p[nj][1] = packf16(s[nj][2], s[nj][3]);
        }

#pragma unroll
        for (int kk = 0; kk < 4; ++kk) {
            const unsigned a0 = p[2 * kk][0],     a1 = p[2 * kk][1];
            const unsigned a2 = p[2 * kk + 1][0], a3 = p[2 * kk + 1][1];
#pragma unroll
            for (int db = 0; db < 8; ++db) {
                unsigned vf[4];
                ldm_x4_t(vf, sV + (kk * 16 + vrow) * APITCH + db * 16 + vcol);
                mma16816h(o[db * 2],     a0, a1, a2, a3, vf[0], vf[1]);
                mma16816h(o[db * 2 + 1], a0, a1, a2, a3, vf[2], vf[3]);
            }
        }
        __syncthreads();
    }

    const float inv0 = 1.f / l0, inv1 = 1.f / l1;
    const int row0 = qt * 128 + wid * 16 + r;
    const size_t base0 = ((size_t)(b * TT + row0)) * CCH + h * HD;
    const size_t base1 = base0 + 8 * CCH;
#pragma unroll
    for (int nj = 0; nj < 16; ++nj) {
        const int d = nj * 8 + 2 * cq;
        bf16 hv, lv;
        split2(o[nj][0] * inv0, hv, lv); g_ahi[base0 + d]     = hv; g_alo[base0 + d]     = lv;
        split2(o[nj][1] * inv0, hv, lv); g_ahi[base0 + d + 1] = hv; g_alo[base0 + d + 1] = lv;
        split2(o[nj][2] * inv1, hv, lv); g_ahi[base1 + d]     = hv; g_alo[base1 + d]     = lv;
        split2(o[nj][3] * inv1, hv, lv); g_ahi[base1 + d + 1] = hv; g_alo[base1 + d + 1] = lv;
    }
}

// ---------------------------------------------------------------------------
extern "C" void kernel_launch(void* const* d_in, const int* in_sizes, int n_in,
                              void* d_out, int out_size)
{
    const float* x    = (const float*)d_in[0];
    const float* cosp = (const float*)d_in[1];
    const float* sinp = (const float*)d_in[2];
    const float* Wq   = (const float*)d_in[3];
    const float* Wk   = (const float*)d_in[4];
    const float* Wv   = (const float*)d_in[5];
    const float* Wo   = (const float*)d_in[6];
    float* out = (float*)d_out;

    cudaFuncSetAttribute(attn_tc,
                         cudaFuncAttributeMaxDynamicSharedMemorySize, ATT_SMEM_BYTES);
    cudaFuncSetAttribute(gemm_tc<0>,
                         cudaFuncAttributeMaxDynamicSharedMemorySize, GEMM_SMEM_BYTES);
    cudaFuncSetAttribute(gemm_tc<1>,
                         cudaFuncAttributeMaxDynamicSharedMemorySize, GEMM_SMEM_BYTES);

    // 0. split conversions
    split_x_kernel<<<(MTOT * CCH) / 256, 256>>>(x);
    tsplit_wqkv<<<dim3(NQKV / 32, CCH / 32), 256>>>(Wq, Wk, Wv);
    tsplit_wo<<<dim3(CCH / 32, CCH / 32), 256>>>(Wo);

    // 1. fused QKV projection
    gemm_tc<0><<<dim3(NQKV / 128, MTOT / 128), 256, GEMM_SMEM_BYTES>>>(nullptr);

    // 2. RoPE + fp16 conversion
    rope_cvt_kernel<<<24576, 256>>>(cosp, sinp);

    // 3. tensor-core causal GQA flash attention
    attn_tc<<<dim3(TT / 128, BB * NH), 256, ATT_SMEM_BYTES>>>();

    // 4. output projection
    gemm_tc<1><<<dim3(CCH / 128, MTOT / 128), 256, GEMM_SMEM_BYTES>>>(out);
}

// round 7
// speedup vs baseline: 5.6481x; 1.2752x over previous
#include <cuda_runtime.h>
#include <cuda_bf16.h>
#include <cuda_fp16.h>
#include <cstdint>

#define BB 2
#define TT 2048
#define CCH 2048
#define NH 16
#define NKV 4
#define HD 128
#define MTOT 4096
#define NQKV 3072

// ---- scratch (no cudaMalloc allowed) ----
__device__ __half g_xh[(size_t)MTOT*CCH], g_xl[(size_t)MTOT*CCH];   // x split [m][k]
__device__ __half g_wqkv[(size_t)NQKV*CCH];                         // W^T fp16 [n][k]
__device__ __half g_wo[(size_t)CCH*CCH];                            // Wo^T fp16 [n][k]
__device__ __half g_ah[(size_t)MTOT*CCH], g_al[(size_t)MTOT*CCH];   // attn out split [m][k]
__device__ float g_q[(size_t)BB*NH*TT*HD];
__device__ float g_k[(size_t)BB*NKV*TT*HD];
__device__ float g_v[(size_t)BB*NKV*TT*HD];
__device__ __half g_qh[(size_t)BB*NH*TT*HD];
__device__ __half g_kh[(size_t)BB*NKV*TT*HD];
__device__ __half g_vh[(size_t)BB*NKV*TT*HD];

__device__ __forceinline__ void split2h(float v, __half& h, __half& l) {
    h = __float2half(v);
    l = __float2half(v - __half2float(h));
}

// ---------------------------------------------------------------------------
// Conversion kernels
// ---------------------------------------------------------------------------
__global__ void split_x_kernel(const float* __restrict__ x) {
    const size_t i = (size_t)blockIdx.x * 256 + threadIdx.x;
    split2h(x[i], g_xh[i], g_xl[i]);
}

// tiled transpose: W[k][n] -> fp16 [n][k]
__global__ void t_wqkv(const float* __restrict__ Wq,
                       const float* __restrict__ Wk,
                       const float* __restrict__ Wv) {
    __shared__ float tile[32][33];
    const int n0 = blockIdx.x * 32, k0 = blockIdx.y * 32;
    const int tx = threadIdx.x & 31, ty = threadIdx.x >> 5;
#pragma unroll
    for (int p = 0; p < 4; ++p) {
        const int r = ty + p * 8;
        const int n = n0 + tx;
        float v;
        if (n0 < 2048)      v = Wq[(size_t)(k0 + r) * 2048 + n];
        else if (n0 < 2560) v = Wk[(size_t)(k0 + r) * 512 + (n - 2048)];
        else                v = Wv[(size_t)(k0 + r) * 512 + (n - 2560)];
        tile[r][tx] = v;
    }
    __syncthreads();
#pragma unroll
    for (int p = 0; p < 4; ++p) {
        const int a = ty + p * 8;
        g_wqkv[(size_t)(n0 + a) * 2048 + k0 + tx] = __float2half(tile[tx][a]);
    }
}

__global__ void t_wo(const float* __restrict__ Wo) {
    __shared__ float tile[32][33];
    const int n0 = blockIdx.x * 32, k0 = blockIdx.y * 32;
    const int tx = threadIdx.x & 31, ty = threadIdx.x >> 5;
#pragma unroll
    for (int p = 0; p < 4; ++p) {
        const int r = ty + p * 8;
        tile[r][tx] = Wo[(size_t)(k0 + r) * 2048 + n0 + tx];
    }
    __syncthreads();
#pragma unroll
    for (int p = 0; p < 4; ++p) {
        const int a = ty + p * 8;
        g_wo[(size_t)(n0 + a) * 2048 + k0 + tx] = __float2half(tile[tx][a]);
    }
}

// ---------------------------------------------------------------------------
// Helpers
// ---------------------------------------------------------------------------
__device__ __forceinline__ uint32_t smem_u32(const void* p) {
    return (uint32_t)__cvta_generic_to_shared(p);
}
__device__ __forceinline__ void ldm_x4(unsigned r[4], const void* p) {
    uint32_t a = smem_u32(p);
    asm volatile("ldmatrix.sync.aligned.m8n8.x4.shared.b16 {%0,%1,%2,%3}, [%4];"
        : "=r"(r[0]), "=r"(r[1]), "=r"(r[2]), "=r"(r[3]) : "r"(a));
}
__device__ __forceinline__ void ldm_x4_t(unsigned r[4], const void* p) {
    uint32_t a = smem_u32(p);
    asm volatile("ldmatrix.sync.aligned.m8n8.x4.trans.shared.b16 {%0,%1,%2,%3}, [%4];"
        : "=r"(r[0]), "=r"(r[1]), "=r"(r[2]), "=r"(r[3]) : "r"(a));
}
__device__ __forceinline__ void mma16816h(float c[4],
    unsigned a0, unsigned a1, unsigned a2, unsigned a3, unsigned b0, unsigned b1)
{
    asm volatile(
        "mma.sync.aligned.m16n8k16.row.col.f32.f16.f16.f32 "
        "{%0,%1,%2,%3},{%4,%5,%6,%7},{%8,%9},{%0,%1,%2,%3};"
        : "+f"(c[0]), "+f"(c[1]), "+f"(c[2]), "+f"(c[3])
        : "r"(a0), "r"(a1), "r"(a2), "r"(a3), "r"(b0), "r"(b1));
}
__device__ __forceinline__ unsigned packf16(float lo, float hi) {
    unsigned d;
    asm("cvt.rn.f16x2.f32 %0, %1, %2;" : "=r"(d) : "f"(hi), "f"(lo));
    return d;
}
__device__ __forceinline__ float ex2(float x) {
    float y; asm("ex2.approx.f32 %0, %1;" : "=f"(y) : "f"(x)); return y;
}
__device__ __forceinline__ void cpasync16(uint32_t smem, const void* gmem) {
    asm volatile("cp.async.cg.shared.global [%0], [%1], 16;" :: "r"(smem), "l"(gmem));
}
#define CP_COMMIT() asm volatile("cp.async.commit_group;")
template<int N> __device__ __forceinline__ void cp_wait() {
    asm volatile("cp.async.wait_group %0;" :: "n"(N));
}

// ---------------------------------------------------------------------------
// fp16 2-term split GEMM: CTA 128(M) x 256(N), BK=32, 8 warps (2x4, 64x64).
// D = Ah*B + Al*B, fp32 accum. cp.async double-buffered.
// ---------------------------------------------------------------------------
#define SPITCH 40
#define AH_OFF 0
#define AL_OFF (128 * SPITCH)
#define BW_OFF (256 * SPITCH)
#define STG_HALVES (512 * SPITCH)
#define G_SMEM_BYTES (2 * STG_HALVES * 2)

template<int MODE>
__global__ __launch_bounds__(256, 1) void gemm_f16(float* __restrict__ out)
{
    extern __shared__ __half sgm[];

    const int tid  = threadIdx.x;
    const int lane = tid & 31;
    const int wid  = tid >> 5;
    const int bm = blockIdx.y * 128;
    const int bn = blockIdx.x * 256;
    const int mw = (wid >> 2) * 64;
    const int nw = (wid & 3) * 64;

    const __half* Ah = (MODE == 0) ? g_xh : g_ah;
    const __half* Al = (MODE == 0) ? g_xl : g_al;
    const __half* Bw = (MODE == 0) ? g_wqkv : g_wo;

    const int lr = tid >> 2;          // 0..63
    const int lc = (tid & 3) * 8;     // chunk col
    const uint32_t sb = smem_u32(sgm);

#define ISSUE(kt)                                                               \
    do {                                                                        \
        const int _k0 = (kt) * 32;                                              \
        const uint32_t _st = sb + (((kt) & 1) * STG_HALVES) * 2;                \
        cpasync16(_st + (AH_OFF + lr * SPITCH + lc) * 2,                        \
                  Ah + (size_t)(bm + lr) * CCH + _k0 + lc);                     \
        cpasync16(_st + (AH_OFF + (lr + 64) * SPITCH + lc) * 2,                 \
                  Ah + (size_t)(bm + lr + 64) * CCH + _k0 + lc);                \
        cpasync16(_st + (AL_OFF + lr * SPITCH + lc) * 2,                        \
                  Al + (size_t)(bm + lr) * CCH + _k0 + lc);                     \
        cpasync16(_st + (AL_OFF + (lr + 64) * SPITCH + lc) * 2,                 \
                  Al + (size_t)(bm + lr + 64) * CCH + _k0 + lc);                \
        cpasync16(_st + (BW_OFF + lr * SPITCH + lc) * 2,                        \
                  Bw + (size_t)(bn + lr) * CCH + _k0 + lc);                     \
        cpasync16(_st + (BW_OFF + (lr + 64) * SPITCH + lc) * 2,                 \
                  Bw + (size_t)(bn + lr + 64) * CCH + _k0 + lc);                \
        cpasync16(_st + (BW_OFF + (lr + 128) * SPITCH + lc) * 2,                \
                  Bw + (size_t)(bn + lr + 128) * CCH + _k0 + lc);               \
        cpasync16(_st + (BW_OFF + (lr + 192) * SPITCH + lc) * 2,                \
                  Bw + (size_t)(bn + lr + 192) * CCH + _k0 + lc);               \
        CP_COMMIT();                                                            \
    } while (0)

    float c[4][8][4];
#pragma unroll
    for (int i = 0; i < 4; ++i)
#pragma unroll
        for (int j = 0; j < 8; ++j)
#pragma unroll
            for (int e = 0; e < 4; ++e) c[i][j][e] = 0.f;

    ISSUE(0);

    const int arow = ((lane >> 3) & 1) * 8 + (lane & 7);
    const int acol = (lane >> 4) * 8;
    const int brow = (lane >> 4) * 8 + (lane & 7);
    const int bcol = ((lane >> 3) & 1) * 8;

    const int NKT = CCH / 32;
    for (int kt = 0; kt < NKT; ++kt) {
        cp_wait<0>();
        __syncthreads();
        if (kt + 1 < NKT) ISSUE(kt + 1);

        __half* st = sgm + (kt & 1) * STG_HALVES;
#pragma unroll
        for (int kk = 0; kk < 2; ++kk) {
            unsigned ah[4][4], al[4][4], bf[4][4];
#pragma unroll
            for (int mi = 0; mi < 4; ++mi) {
                const int off = (mw + mi * 16 + arow) * SPITCH + kk * 16 + acol;
                ldm_x4(ah[mi], st + AH_OFF + off);
                ldm_x4(al[mi], st + AL_OFF + off);
            }
#pragma unroll
            for (int x = 0; x < 4; ++x) {
                const int off = (nw + x * 16 + brow) * SPITCH + kk * 16 + bcol;
                ldm_x4(bf[x], st + BW_OFF + off);
            }
#pragma unroll
            for (int mi = 0; mi < 4; ++mi) {
#pragma unroll
                for (int nj = 0; nj < 8; ++nj) {
                    const int x = nj >> 1, y = (nj & 1) * 2;
                    mma16816h(c[mi][nj], ah[mi][0], ah[mi][1], ah[mi][2], ah[mi][3],
                              bf[x][y], bf[x][y + 1]);
                    mma16816h(c[mi][nj], al[mi][0], al[mi][1], al[mi][2], al[mi][3],
                              bf[x][y], bf[x][y + 1]);
                }
            }
        }
        __syncthreads();
    }

    // epilogue
#pragma unroll
    for (int mi = 0; mi < 4; ++mi) {
#pragma unroll
        for (int nj = 0; nj < 8; ++nj) {
            const int m = bm + mw + mi * 16 + (lane >> 2);
            const int n = bn + nw + nj * 8 + 2 * (lane & 3);
            const float2 v0 = make_float2(c[mi][nj][0], c[mi][nj][1]);
            const float2 v1 = make_float2(c[mi][nj][2], c[mi][nj][3]);
            if (MODE == 1) {
                *(float2*)(out + (size_t)m * 2048 + n)       = v0;
                *(float2*)(out + (size_t)(m + 8) * 2048 + n) = v1;
            } else {
                const int b = m >> 11, t = m & 2047;
                const int d = n & 127;
                float* dst;
                if (n < 2048) {
                    dst = g_q + ((size_t)(b * NH + (n >> 7)) * TT + t) * HD + d;
                } else if (n < 2560) {
                    dst = g_k + ((size_t)(b * NKV + ((n - 2048) >> 7)) * TT + t) * HD + d;
                } else {
                    dst = g_v + ((size_t)(b * NKV + ((n - 2560) >> 7)) * TT + t) * HD + d;
                }
                *(float2*)dst = v0;
                *(float2*)(dst + 8 * HD) = v1;
            }
        }
    }
}

// ---------------------------------------------------------------------------
// RoPE + fp16 conversion (q pre-scaled by 1/sqrt(HD)*log2e)
// ---------------------------------------------------------------------------
__global__ void rope_cvt_kernel(const float* __restrict__ cosp,
                                const float* __restrict__ sinp)
{
    const int i = blockIdx.x * 256 + threadIdx.x;
    const int nq = 1 << 22;
    const int nk = 1 << 20;
    const int nv = 1 << 20;

    if (i < nq) {
        const int d = i & 63, t = (i >> 6) & 2047, bh = i >> 17;
        const float* src = g_q + ((size_t)bh * TT + t) * HD;
        __half* dst = g_qh + ((size_t)bh * TT + t) * HD;
        const float SC = 0.08838834764831845f * 1.44269504088896341f;
        const float c0 = cosp[t * HD + d],      s0 = sinp[t * HD + d];
        const float c1 = cosp[t * HD + d + 64], s1 = sinp[t * HD + d + 64];
        const float x0 = src[d], x1 = src[d + 64];
        dst[d]      = __float2half((x0 * c0 - x1 * s0) * SC);
        dst[d + 64] = __float2half((x1 * c1 + x0 * s1) * SC);
    } else if (i < nq + nk) {
        const int i2 = i - nq;
        const int d = i2 & 63, t = (i2 >> 6) & 2047, bkv = i2 >> 17;
        const float* src = g_k + ((size_t)bkv * TT + t) * HD;
        __half* dst = g_kh + ((size_t)bkv * TT + t) * HD;
        const float c0 = cosp[t * HD + d],      s0 = sinp[t * HD + d];
        const float c1 = cosp[t * HD + d + 64], s1 = sinp[t * HD + d + 64];
        const float x0 = src[d], x1 = src[d + 64];
        dst[d]      = __float2half(x0 * c0 - x1 * s0);
        dst[d + 64] = __float2half(x1 * c1 + x0 * s1);
    } else if (i < nq + nk + nv) {
        const int i3 = i - nq - nk;
        const int d = i3 & 63, t = (i3 >> 6) & 2047, bkv = i3 >> 17;
        const float* src = g_v + ((size_t)bkv * TT + t) * HD;
        __half* dst = g_vh + ((size_t)bkv * TT + t) * HD;
        dst[d]      = __float2half(src[d]);
        dst[d + 64] = __float2half(src[d + 64]);
    }
}

// ---------------------------------------------------------------------------
// Tensor-core flash attention (epilogue -> fp16 hi/lo for GEMM2)
// ---------------------------------------------------------------------------
#define APITCH 136
#define ATT_SMEM_BYTES ((128 + 64 + 64) * APITCH * 2)

__global__ __launch_bounds__(256, 1) void attn_tc()
{
    extern __shared__ __half sh2[];
    __half* sQ = sh2;
    __half* sK = sh2 + 128 * APITCH;
    __half* sV = sh2 + 192 * APITCH;

    const int tid = threadIdx.x;
    const int wid = tid >> 5, lane = tid & 31;
    const int r = lane >> 2, cq = lane & 3;
    const int qt = (int)gridDim.x - 1 - (int)blockIdx.x;
    const int bh = blockIdx.y;
    const int b = bh >> 4, h = bh & 15, kvh = h >> 2;

    const uint4* qg = (const uint4*)(g_qh + (size_t)bh * TT * HD + (size_t)qt * 128 * HD);
    const uint4* kg = (const uint4*)(g_kh + (size_t)(b * NKV + kvh) * TT * HD);
    const uint4* vg = (const uint4*)(g_vh + (size_t)(b * NKV + kvh) * TT * HD);

#pragma unroll
    for (int it = 0; it < 8; ++it) {
        const int idx = it * 256 + tid;
        *(uint4*)&sQ[(idx >> 4) * APITCH + (idx & 15) * 8] = qg[idx];
    }
    __syncthreads();

    unsigned qf[8][4];
    {
        const int arow = wid * 16 + (lane & 15);
        const int acol = (lane >> 4) * 8;
#pragma unroll
        for (int kk = 0; kk < 8; ++kk)
            ldm_x4(qf[kk], sQ + arow * APITCH + kk * 16 + acol);
    }

    float o[16][4];
#pragma unroll
    for (int nj = 0; nj < 16; ++nj)
#pragma unroll
        for (int e = 0; e < 4; ++e) o[nj][e] = 0.f;
    float m0 = -1e30f, m1 = -1e30f, l0 = 0.f, l1 = 0.f;

    const int krow = (lane & 7) + ((lane >> 4) << 3);
    const int kcol = ((lane >> 3) & 1) * 8;
    const int vrow = lane & 15;
    const int vcol = (lane >> 4) * 8;

    const int ntiles = 2 * qt + 2;
    for (int kt = 0; kt < ntiles; ++kt) {
#pragma unroll
        for (int it = 0; it < 4; ++it) {
            const int idx = it * 256 + tid;
            const int row = idx >> 4, q8 = (idx & 15) * 8;
            *(uint4*)&sK[row * APITCH + q8] = kg[(size_t)kt * 1024 + idx];
            *(uint4*)&sV[row * APITCH + q8] = vg[(size_t)kt * 1024 + idx];
        }
        __syncthreads();

        float s[8][4];
#pragma unroll
        for (int nj = 0; nj < 8; ++nj)
#pragma unroll
            for (int e = 0; e < 4; ++e) s[nj][e] = 0.f;

#pragma unroll
        for (int kk = 0; kk < 8; ++kk) {
#pragma unroll
            for (int nb = 0; nb < 4; ++nb) {
                unsigned kf[4];
                ldm_x4(kf, sK + (nb * 16 + krow) * APITCH + kk * 16 + kcol);
                mma16816h(s[nb * 2],     qf[kk][0], qf[kk][1], qf[kk][2], qf[kk][3], kf[0], kf[1]);
                mma16816h(s[nb * 2 + 1], qf[kk][0], qf[kk][1], qf[kk][2], qf[kk][3], kf[2], kf[3]);
            }
        }

        if (kt >= 2 * qt) {
            const int row0 = qt * 128 + wid * 16 + r;
#pragma unroll
            for (int nj = 0; nj < 8; ++nj) {
                const int key = kt * 64 + nj * 8 + 2 * cq;
                if (key > row0)         s[nj][0] = -1e30f;
                if (key + 1 > row0)     s[nj][1] = -1e30f;
                if (key > row0 + 8)     s[nj][2] = -1e30f;
                if (key + 1 > row0 + 8) s[nj][3] = -1e30f;
            }
        }

        float mx0 = s[0][0], mx1 = s[0][2];
#pragma unroll
        for (int nj = 0; nj < 8; ++nj) {
            mx0 = fmaxf(mx0, fmaxf(s[nj][0], s[nj][1]));
            mx1 = fmaxf(mx1, fmaxf(s[nj][2], s[nj][3]));
        }
        mx0 = fmaxf(mx0, __shfl_xor_sync(0xffffffffu, mx0, 1));
        mx0 = fmaxf(mx0, __shfl_xor_sync(0xffffffffu, mx0, 2));
        mx1 = fmaxf(mx1, __shfl_xor_sync(0xffffffffu, mx1, 1));
        mx1 = fmaxf(mx1, __shfl_xor_sync(0xffffffffu, mx1, 2));

        const float mn0 = fmaxf(m0, mx0), mn1 = fmaxf(m1, mx1);
        const float cr0 = ex2(m0 - mn0),  cr1 = ex2(m1 - mn1);
        m0 = mn0; m1 = mn1;

        float sum0 = 0.f, sum1 = 0.f;
#pragma unroll
        for (int nj = 0; nj < 8; ++nj) {
            s[nj][0] = ex2(s[nj][0] - mn0); sum0 += s[nj][0];
            s[nj][1] = ex2(s[nj][1] - mn0); sum0 += s[nj][1];
            s[nj][2] = ex2(s[nj][2] - mn1); sum1 += s[nj][2];
            s[nj][3] = ex2(s[nj][3] - mn1); sum1 += s[nj][3];
        }
        sum0 += __shfl_xor_sync(0xffffffffu, sum0, 1);
        sum0 += __shfl_xor_sync(0xffffffffu, sum0, 2);
        sum1 += __shfl_xor_sync(0xffffffffu, sum1, 1);
        sum1 += __shfl_xor_sync(0xffffffffu, sum1, 2);
        l0 = l0 * cr0 + sum0;
        l1 = l1 * cr1 + sum1;

#pragma unroll
        for (int nj = 0; nj < 16; ++nj) {
            o[nj][0] *= cr0; o[nj][1] *= cr0;
            o[nj][2] *= cr1; o[nj][3] *= cr1;
        }

        unsigned p[8][2];
#pragma unroll
        for (int nj = 0; nj < 8; ++nj) {
            p[nj][0] = packf16(s[nj][0], s[nj][1]);
            p[nj][1] = packf16(s[nj][2], s[nj][3]);
        }

#pragma unroll
        for (int kk = 0; kk < 4; ++kk) {
            const unsigned a0 = p[2 * kk][0],     a1 = p[2 * kk][1];
            const unsigned a2 = p[2 * kk + 1][0], a3 = p[2 * kk + 1][1];
#pragma unroll
            for (int db = 0; db < 8; ++db) {
                unsigned vf[4];
                ldm_x4_t(vf, sV + (kk * 16 + vrow) * APITCH + db * 16 + vcol);
                mma16816h(o[db * 2],     a0, a1, a2, a3, vf[0], vf[1]);
                mma16816h(o[db * 2 + 1], a0, a1, a2, a3, vf[2], vf[3]);
            }
        }
        __syncthreads();
    }

    const float inv0 = 1.f / l0, inv1 = 1.f / l1;
    const int row0 = qt * 128 + wid * 16 + r;
    const size_t base0 = ((size_t)(b * TT + row0)) * CCH + h * HD;
    const size_t base1 = base0 + 8 * CCH;
#pragma unroll
    for (int nj = 0; nj < 16; ++nj) {
        const int d = nj * 8 + 2 * cq;
        __half hv, lv;
        split2h(o[nj][0] * inv0, hv, lv); g_ah[base0 + d]     = hv; g_al[base0 + d]     = lv;
        split2h(o[nj][1] * inv0, hv, lv); g_ah[base0 + d + 1] = hv; g_al[base0 + d + 1] = lv;
        split2h(o[nj][2] * inv1, hv, lv); g_ah[base1 + d]     = hv; g_al[base1 + d]     = lv;
        split2h(o[nj][3] * inv1, hv, lv); g_ah[base1 + d + 1] = hv; g_al[base1 + d + 1] = lv;
    }
}

// ---------------------------------------------------------------------------
extern "C" void kernel_launch(void* const* d_in, const int* in_sizes, int n_in,
                              void* d_out, int out_size)
{
    const float* x    = (const float*)d_in[0];
    const float* cosp = (const float*)d_in[1];
    const float* sinp = (const float*)d_in[2];
    const float* Wq   = (const float*)d_in[3];
    const float* Wk   = (const float*)d_in[4];
    const float* Wv   = (const float*)d_in[5];
    const float* Wo   = (const float*)d_in[6];
    float* out = (float*)d_out;

    cudaFuncSetAttribute(attn_tc,
                         cudaFuncAttributeMaxDynamicSharedMemorySize, ATT_SMEM_BYTES);
    cudaFuncSetAttribute(gemm_f16<0>,
                         cudaFuncAttributeMaxDynamicSharedMemorySize, G_SMEM_BYTES);
    cudaFuncSetAttribute(gemm_f16<1>,
                         cudaFuncAttributeMaxDynamicSharedMemorySize, G_SMEM_BYTES);

    // 0. conversions
    split_x_kernel<<<(MTOT * CCH) / 256, 256>>>(x);
    t_wqkv<<<dim3(NQKV / 32, CCH / 32), 256>>>(Wq, Wk, Wv);
    t_wo<<<dim3(CCH / 32, CCH / 32), 256>>>(Wo);

    // 1. fused QKV projection
    gemm_f16<0><<<dim3(NQKV / 256, MTOT / 128), 256, G_SMEM_BYTES>>>(nullptr);

    // 2. RoPE + fp16 conversion
    rope_cvt_kernel<<<24576, 256>>>(cosp, sinp);

    // 3. tensor-core causal GQA flash attention
    attn_tc<<<dim3(TT / 128, BB * NH), 256, ATT_SMEM_BYTES>>>();

    // 4. output projection
    gemm_f16<1><<<dim3(CCH / 256, MTOT / 128), 256, G_SMEM_BYTES>>>(out);
}

// round 8
// speedup vs baseline: 8.1273x; 1.4390x over previous
#include <cuda_runtime.h>
#include <cuda_fp16.h>
#include <cstdint>

#define BB 2
#define TT 2048
#define CCH 2048
#define NH 16
#define NKV 4
#define HD 128
#define MTOT 4096
#define NQKV 3072

// ---- scratch (no cudaMalloc allowed) ----
__device__ __half g_xh[(size_t)MTOT*CCH];      // x fp16 [m][k]
__device__ __half g_wqkv[(size_t)NQKV*CCH];    // W^T fp16 [n][k]
__device__ __half g_wo[(size_t)CCH*CCH];       // Wo^T fp16 [n][k]
__device__ __half g_ah[(size_t)MTOT*CCH];      // attn out fp16 [m][k]
__device__ __half g_qh[(size_t)BB*NH*TT*HD];
__device__ __half g_kh[(size_t)BB*NKV*TT*HD];
__device__ __half g_vh[(size_t)BB*NKV*TT*HD];

// ---------------------------------------------------------------------------
// Conversion kernels
// ---------------------------------------------------------------------------
__global__ void cvt_x_kernel(const float* __restrict__ x) {
    const size_t i = (size_t)blockIdx.x * 256 + threadIdx.x;
    g_xh[i] = __float2half(x[i]);
}

__global__ void t_wqkv(const float* __restrict__ Wq,
                       const float* __restrict__ Wk,
                       const float* __restrict__ Wv) {
    __shared__ float tile[32][33];
    const int n0 = blockIdx.x * 32, k0 = blockIdx.y * 32;
    const int tx = threadIdx.x & 31, ty = threadIdx.x >> 5;
#pragma unroll
    for (int p = 0; p < 4; ++p) {
        const int r = ty + p * 8;
        const int n = n0 + tx;
        float v;
        if (n0 < 2048)      v = Wq[(size_t)(k0 + r) * 2048 + n];
        else if (n0 < 2560) v = Wk[(size_t)(k0 + r) * 512 + (n - 2048)];
        else                v = Wv[(size_t)(k0 + r) * 512 + (n - 2560)];
        tile[r][tx] = v;
    }
    __syncthreads();
#pragma unroll
    for (int p = 0; p < 4; ++p) {
        const int a = ty + p * 8;
        g_wqkv[(size_t)(n0 + a) * 2048 + k0 + tx] = __float2half(tile[tx][a]);
    }
}

__global__ void t_wo(const float* __restrict__ Wo) {
    __shared__ float tile[32][33];
    const int n0 = blockIdx.x * 32, k0 = blockIdx.y * 32;
    const int tx = threadIdx.x & 31, ty = threadIdx.x >> 5;
#pragma unroll
    for (int p = 0; p < 4; ++p) {
        const int r = ty + p * 8;
        tile[r][tx] = Wo[(size_t)(k0 + r) * 2048 + n0 + tx];
    }
    __syncthreads();
#pragma unroll
    for (int p = 0; p < 4; ++p) {
        const int a = ty + p * 8;
        g_wo[(size_t)(n0 + a) * 2048 + k0 + tx] = __float2half(tile[tx][a]);
    }
}

// ---------------------------------------------------------------------------
// Helpers
// ---------------------------------------------------------------------------
__device__ __forceinline__ uint32_t smem_u32(const void* p) {
    return (uint32_t)__cvta_generic_to_shared(p);
}
__device__ __forceinline__ void ldm_x4(unsigned r[4], const void* p) {
    uint32_t a = smem_u32(p);
    asm volatile("ldmatrix.sync.aligned.m8n8.x4.shared.b16 {%0,%1,%2,%3}, [%4];"
        : "=r"(r[0]), "=r"(r[1]), "=r"(r[2]), "=r"(r[3]) : "r"(a));
}
__device__ __forceinline__ void ldm_x4_t(unsigned r[4], const void* p) {
    uint32_t a = smem_u32(p);
    asm volatile("ldmatrix.sync.aligned.m8n8.x4.trans.shared.b16 {%0,%1,%2,%3}, [%4];"
        : "=r"(r[0]), "=r"(r[1]), "=r"(r[2]), "=r"(r[3]) : "r"(a));
}
__device__ __forceinline__ void mma16816h(float c[4],
    unsigned a0, unsigned a1, unsigned a2, unsigned a3, unsigned b0, unsigned b1)
{
    asm volatile(
        "mma.sync.aligned.m16n8k16.row.col.f32.f16.f16.f32 "
        "{%0,%1,%2,%3},{%4,%5,%6,%7},{%8,%9},{%0,%1,%2,%3};"
        : "+f"(c[0]), "+f"(c[1]), "+f"(c[2]), "+f"(c[3])
        : "r"(a0), "r"(a1), "r"(a2), "r"(a3), "r"(b0), "r"(b1));
}
__device__ __forceinline__ unsigned packf16(float lo, float hi) {
    unsigned d;
    asm("cvt.rn.f16x2.f32 %0, %1, %2;" : "=r"(d) : "f"(hi), "f"(lo));
    return d;
}
__device__ __forceinline__ float ex2(float x) {
    float y; asm("ex2.approx.f32 %0, %1;" : "=f"(y) : "f"(x)); return y;
}
__device__ __forceinline__ void cpasync16(uint32_t smem, const void* gmem) {
    asm volatile("cp.async.cg.shared.global [%0], [%1], 16;" :: "r"(smem), "l"(gmem));
}
#define CP_COMMIT() asm volatile("cp.async.commit_group;")
template<int N> __device__ __forceinline__ void cp_wait() {
    asm volatile("cp.async.wait_group %0;" :: "n"(N));
}

// ---------------------------------------------------------------------------
// Plain fp16 GEMM: CTA 128(M) x 256(N), BK=32, 8 warps (2x4, each 64x64).
// 3-stage cp.async ring, one barrier per k-tile.
// MODE 0: A=g_xh, B=g_wqkv -> fp16 q/k/v (head-major). MODE 1: A=g_ah, B=g_wo -> fp32 out.
// ---------------------------------------------------------------------------
#define SPITCH 40
#define A_OFF 0
#define B_OFF (128 * SPITCH)
#define STG_HALVES (384 * SPITCH)
#define NSTG 3
#define G_SMEM_BYTES (NSTG * STG_HALVES * 2)

template<int MODE>
__global__ __launch_bounds__(256, 1) void gemm_f16(float* __restrict__ out)
{
    extern __shared__ __half sgm[];

    const int tid  = threadIdx.x;
    const int lane = tid & 31;
    const int wid  = tid >> 5;
    const int bm = blockIdx.y * 128;
    const int bn = blockIdx.x * 256;
    const int mw = (wid >> 2) * 64;
    const int nw = (wid & 3) * 64;

    const __half* Ax = (MODE == 0) ? g_xh : g_ah;
    const __half* Bw = (MODE == 0) ? g_wqkv : g_wo;

    const int lr = tid >> 2;          // 0..63
    const int lc = (tid & 3) * 8;     // chunk col (halves)
    const uint32_t sb = smem_u32(sgm);

#define ISSUE(kt)                                                               \
    do {                                                                        \
        const int _k0 = (kt) * 32;                                              \
        const uint32_t _st = sb + (((kt) % NSTG) * STG_HALVES) * 2;             \
        cpasync16(_st + (A_OFF + lr * SPITCH + lc) * 2,                         \
                  Ax + (size_t)(bm + lr) * CCH + _k0 + lc);                     \
        cpasync16(_st + (A_OFF + (lr + 64) * SPITCH + lc) * 2,                  \
                  Ax + (size_t)(bm + lr + 64) * CCH + _k0 + lc);                \
        cpasync16(_st + (B_OFF + lr * SPITCH + lc) * 2,                         \
                  Bw + (size_t)(bn + lr) * CCH + _k0 + lc);                     \
        cpasync16(_st + (B_OFF + (lr + 64) * SPITCH + lc) * 2,                  \
                  Bw + (size_t)(bn + lr + 64) * CCH + _k0 + lc);                \
        cpasync16(_st + (B_OFF + (lr + 128) * SPITCH + lc) * 2,                 \
                  Bw + (size_t)(bn + lr + 128) * CCH + _k0 + lc);               \
        cpasync16(_st + (B_OFF + (lr + 192) * SPITCH + lc) * 2,                 \
                  Bw + (size_t)(bn + lr + 192) * CCH + _k0 + lc);               \
        CP_COMMIT();                                                            \
    } while (0)

    float c[4][8][4];
#pragma unroll
    for (int i = 0; i < 4; ++i)
#pragma unroll
        for (int j = 0; j < 8; ++j)
#pragma unroll
            for (int e = 0; e < 4; ++e) c[i][j][e] = 0.f;

    ISSUE(0);
    ISSUE(1);

    const int arow = ((lane >> 3) & 1) * 8 + (lane & 7);
    const int acol = (lane >> 4) * 8;
    const int brow = (lane >> 4) * 8 + (lane & 7);
    const int bcol = ((lane >> 3) & 1) * 8;

    const int NKT = CCH / 32;
    for (int kt = 0; kt < NKT; ++kt) {
        cp_wait<1>();
        __syncthreads();
        if (kt + 2 < NKT) ISSUE(kt + 2);

        __half* st = sgm + (kt % NSTG) * STG_HALVES;
#pragma unroll
        for (int kk = 0; kk < 2; ++kk) {
            unsigned af[4][4], bf[4][4];
#pragma unroll
            for (int mi = 0; mi < 4; ++mi)
                ldm_x4(af[mi], st + A_OFF + (mw + mi * 16 + arow) * SPITCH + kk * 16 + acol);
#pragma unroll
            for (int x = 0; x < 4; ++x)
                ldm_x4(bf[x], st + B_OFF + (nw + x * 16 + brow) * SPITCH + kk * 16 + bcol);
#pragma unroll
            for (int mi = 0; mi < 4; ++mi) {
#pragma unroll
                for (int nj = 0; nj < 8; ++nj) {
                    const int x = nj >> 1, y = (nj & 1) * 2;
                    mma16816h(c[mi][nj], af[mi][0], af[mi][1], af[mi][2], af[mi][3],
                              bf[x][y], bf[x][y + 1]);
                }
            }
        }
    }

    // epilogue
#pragma unroll
    for (int mi = 0; mi < 4; ++mi) {
#pragma unroll
        for (int nj = 0; nj < 8; ++nj) {
            const int m = bm + mw + mi * 16 + (lane >> 2);
            const int n = bn + nw + nj * 8 + 2 * (lane & 3);
            if (MODE == 1) {
                *(float2*)(out + (size_t)m * 2048 + n) =
                    make_float2(c[mi][nj][0], c[mi][nj][1]);
                *(float2*)(out + (size_t)(m + 8) * 2048 + n) =
                    make_float2(c[mi][nj][2], c[mi][nj][3]);
            } else {
                const int b = m >> 11, t = m & 2047;
                const int d = n & 127;
                __half* dst;
                if (n < 2048) {
                    dst = g_qh + ((size_t)(b * NH + (n >> 7)) * TT + t) * HD + d;
                } else if (n < 2560) {
                    dst = g_kh + ((size_t)(b * NKV + ((n - 2048) >> 7)) * TT + t) * HD + d;
                } else {
                    dst = g_vh + ((size_t)(b * NKV + ((n - 2560) >> 7)) * TT + t) * HD + d;
                }
                *(unsigned*)dst            = packf16(c[mi][nj][0], c[mi][nj][1]);
                *(unsigned*)(dst + 8 * HD) = packf16(c[mi][nj][2], c[mi][nj][3]);
            }
        }
    }
}

// ---------------------------------------------------------------------------
// RoPE in place on fp16 g_qh (scaled by 1/sqrt(HD)*log2e) and g_kh.
// ---------------------------------------------------------------------------
__global__ void rope_kernel(const float* __restrict__ cosp,
                            const float* __restrict__ sinp)
{
    const int i = blockIdx.x * 256 + threadIdx.x;
    const int nq = 1 << 22;          // BB*NH*TT*64
    const int nk = 1 << 20;          // BB*NKV*TT*64
    __half* base;
    int t, d;
    float sc;
    if (i < nq) {
        d = i & 63; t = (i >> 6) & 2047;
        base = g_qh + ((size_t)(i >> 17) * TT + t) * HD;
        sc = 0.08838834764831845f * 1.44269504088896341f;
    } else if (i < nq + nk) {
        const int i2 = i - nq;
        d = i2 & 63; t = (i2 >> 6) & 2047;
        base = g_kh + ((size_t)(i2 >> 17) * TT + t) * HD;
        sc = 1.f;
    } else return;

    const float c0 = cosp[t * HD + d],      s0 = sinp[t * HD + d];
    const float c1 = cosp[t * HD + d + 64], s1 = sinp[t * HD + d + 64];
    const float x0 = __half2float(base[d]), x1 = __half2float(base[d + 64]);
    base[d]      = __float2half((x0 * c0 - x1 * s0) * sc);
    base[d + 64] = __float2half((x1 * c1 + x0 * s1) * sc);
}

// ---------------------------------------------------------------------------
// Tensor-core flash attention (epilogue -> fp16 g_ah)
// ---------------------------------------------------------------------------
#define APITCH 136
#define ATT_SMEM_BYTES ((128 + 64 + 64) * APITCH * 2)

__global__ __launch_bounds__(256, 1) void attn_tc()
{
    extern __shared__ __half sh2[];
    __half* sQ = sh2;
    __half* sK = sh2 + 128 * APITCH;
    __half* sV = sh2 + 192 * APITCH;

    const int tid = threadIdx.x;
    const int wid = tid >> 5, lane = tid & 31;
    const int r = lane >> 2, cq = lane & 3;
    const int qt = (int)gridDim.x - 1 - (int)blockIdx.x;
    const int bh = blockIdx.y;
    const int b = bh >> 4, h = bh & 15, kvh = h >> 2;

    const uint4* qg = (const uint4*)(g_qh + (size_t)bh * TT * HD + (size_t)qt * 128 * HD);
    const uint4* kg = (const uint4*)(g_kh + (size_t)(b * NKV + kvh) * TT * HD);
    const uint4* vg = (const uint4*)(g_vh + (size_t)(b * NKV + kvh) * TT * HD);

#pragma unroll
    for (int it = 0; it < 8; ++it) {
        const int idx = it * 256 + tid;
        *(uint4*)&sQ[(idx >> 4) * APITCH + (idx & 15) * 8] = qg[idx];
    }
    __syncthreads();

    unsigned qf[8][4];
    {
        const int arow = wid * 16 + (lane & 15);
        const int acol = (lane >> 4) * 8;
#pragma unroll
        for (int kk = 0; kk < 8; ++kk)
            ldm_x4(qf[kk], sQ + arow * APITCH + kk * 16 + acol);
    }

    float o[16][4];
#pragma unroll
    for (int nj = 0; nj < 16; ++nj)
#pragma unroll
        for (int e = 0; e < 4; ++e) o[nj][e] = 0.f;
    float m0 = -1e30f, m1 = -1e30f, l0 = 0.f, l1 = 0.f;

    const int krow = (lane & 7) + ((lane >> 4) << 3);
    const int kcol = ((lane >> 3) & 1) * 8;
    const int vrow = lane & 15;
    const int vcol = (lane >> 4) * 8;

    const int ntiles = 2 * qt + 2;
    for (int kt = 0; kt < ntiles; ++kt) {
#pragma unroll
        for (int it = 0; it < 4; ++it) {
            const int idx = it * 256 + tid;
            const int row = idx >> 4, q8 = (idx & 15) * 8;
            *(uint4*)&sK[row * APITCH + q8] = kg[(size_t)kt * 1024 + idx];
            *(uint4*)&sV[row * APITCH + q8] = vg[(size_t)kt * 1024 + idx];
        }
        __syncthreads();

        float s[8][4];
#pragma unroll
        for (int nj = 0; nj < 8; ++nj)
#pragma unroll
            for (int e = 0; e < 4; ++e) s[nj][e] = 0.f;

#pragma unroll
        for (int kk = 0; kk < 8; ++kk) {
#pragma unroll
            for (int nb = 0; nb < 4; ++nb) {
                unsigned kf[4];
                ldm_x4(kf, sK + (nb * 16 + krow) * APITCH + kk * 16 + kcol);
                mma16816h(s[nb * 2],     qf[kk][0], qf[kk][1], qf[kk][2], qf[kk][3], kf[0], kf[1]);
                mma16816h(s[nb * 2 + 1], qf[kk][0], qf[kk][1], qf[kk][2], qf[kk][3], kf[2], kf[3]);
            }
        }

        if (kt >= 2 * qt) {
            const int row0 = qt * 128 + wid * 16 + r;
#pragma unroll
            for (int nj = 0; nj < 8; ++nj) {
                const int key = kt * 64 + nj * 8 + 2 * cq;
                if (key > row0)         s[nj][0] = -1e30f;
                if (key + 1 > row0)     s[nj][1] = -1e30f;
                if (key > row0 + 8)     s[nj][2] = -1e30f;
                if (key + 1 > row0 + 8) s[nj][3] = -1e30f;
            }
        }

        float mx0 = s[0][0], mx1 = s[0][2];
#pragma unroll
        for (int nj = 0; nj < 8; ++nj) {
            mx0 = fmaxf(mx0, fmaxf(s[nj][0], s[nj][1]));
            mx1 = fmaxf(mx1, fmaxf(s[nj][2], s[nj][3]));
        }
        mx0 = fmaxf(mx0, __shfl_xor_sync(0xffffffffu, mx0, 1));
        mx0 = fmaxf(mx0, __shfl_xor_sync(0xffffffffu, mx0, 2));
        mx1 = fmaxf(mx1, __shfl_xor_sync(0xffffffffu, mx1, 1));
        mx1 = fmaxf(mx1, __shfl_xor_sync(0xffffffffu, mx1, 2));

        const float mn0 = fmaxf(m0, mx0), mn1 = fmaxf(m1, mx1);
        const float cr0 = ex2(m0 - mn0),  cr1 = ex2(m1 - mn1);
        m0 = mn0; m1 = mn1;

        float sum0 = 0.f, sum1 = 0.f;
#pragma unroll
        for (int nj = 0; nj < 8; ++nj) {
            s[nj][0] = ex2(s[nj][0] - mn0); sum0 += s[nj][0];
            s[nj][1] = ex2(s[nj][1] - mn0); sum0 += s[nj][1];
            s[nj][2] = ex2(s[nj][2] - mn1); sum1 += s[nj][2];
            s[nj][3] = ex2(s[nj][3] - mn1); sum1 += s[nj][3];
        }
        sum0 += __shfl_xor_sync(0xffffffffu, sum0, 1);
        sum0 += __shfl_xor_sync(0xffffffffu, sum0, 2);
        sum1 += __shfl_xor_sync(0xffffffffu, sum1, 1);
        sum1 += __shfl_xor_sync(0xffffffffu, sum1, 2);
        l0 = l0 * cr0 + sum0;
        l1 = l1 * cr1 + sum1;

#pragma unroll
        for (int nj = 0; nj < 16; ++nj) {
            o[nj][0] *= cr0; o[nj][1] *= cr0;
            o[nj][2] *= cr1; o[nj][3] *= cr1;
        }

        unsigned p[8][2];
#pragma unroll
        for (int nj = 0; nj < 8; ++nj) {
            p[nj][0] = packf16(s[nj][0], s[nj][1]);
            p[nj][1] = packf16(s[nj][2], s[nj][3]);
        }

#pragma unroll
        for (int kk = 0; kk < 4; ++kk) {
            const unsigned a0 = p[2 * kk][0],     a1 = p[2 * kk][1];
            const unsigned a2 = p[2 * kk + 1][0], a3 = p[2 * kk + 1][1];
#pragma unroll
            for (int db = 0; db < 8; ++db) {
                unsigned vf[4];
                ldm_x4_t(vf, sV + (kk * 16 + vrow) * APITCH + db * 16 + vcol);
                mma16816h(o[db * 2],     a0, a1, a2, a3, vf[0], vf[1]);
                mma16816h(o[db * 2 + 1], a0, a1, a2, a3, vf[2], vf[3]);
            }
        }
        __syncthreads();
    }

    const float inv0 = 1.f / l0, inv1 = 1.f / l1;
    const int row0 = qt * 128 + wid * 16 + r;
    const size_t base0 = ((size_t)(b * TT + row0)) * CCH + h * HD;
    const size_t base1 = base0 + 8 * CCH;
#pragma unroll
    for (int nj = 0; nj < 16; ++nj) {
        const int d = nj * 8 + 2 * cq;
        *(unsigned*)(g_ah + base0 + d) = packf16(o[nj][0] * inv0, o[nj][1] * inv0);
        *(unsigned*)(g_ah + base1 + d) = packf16(o[nj][2] * inv1, o[nj][3] * inv1);
    }
}

// ---------------------------------------------------------------------------
extern "C" void kernel_launch(void* const* d_in, const int* in_sizes, int n_in,
                              void* d_out, int out_size)
{
    const float* x    = (const float*)d_in[0];
    const float* cosp = (const float*)d_in[1];
    const float* sinp = (const float*)d_in[2];
    const float* Wq   = (const float*)d_in[3];
    const float* Wk   = (const float*)d_in[4];
    const float* Wv   = (const float*)d_in[5];
    const float* Wo   = (const float*)d_in[6];
    float* out = (float*)d_out;

    cudaFuncSetAttribute(attn_tc,
                         cudaFuncAttributeMaxDynamicSharedMemorySize, ATT_SMEM_BYTES);
    cudaFuncSetAttribute(gemm_f16<0>,
                         cudaFuncAttributeMaxDynamicSharedMemorySize, G_SMEM_BYTES);
    cudaFuncSetAttribute(gemm_f16<1>,
                         cudaFuncAttributeMaxDynamicSharedMemorySize, G_SMEM_BYTES);

    // 0. conversions
    cvt_x_kernel<<<(MTOT * CCH) / 256, 256>>>(x);
    t_wqkv<<<dim3(NQKV / 32, CCH / 32), 256>>>(Wq, Wk, Wv);
    t_wo<<<dim3(CCH / 32, CCH / 32), 256>>>(Wo);

    // 1. fused QKV projection -> fp16 q/k/v
    gemm_f16<0><<<dim3(NQKV / 256, MTOT / 128), 256, G_SMEM_BYTES>>>(nullptr);

    // 2. RoPE in place (fp16)
    rope_kernel<<<((1 << 22) + (1 << 20)) / 256, 256>>>(cosp, sinp);

    // 3. tensor-core causal GQA flash attention
    attn_tc<<<dim3(TT / 128, BB * NH), 256, ATT_SMEM_BYTES>>>();

    // 4. output projection
    gemm_f16<1><<<dim3(CCH / 256, MTOT / 128), 256, G_SMEM_BYTES>>>(out);
}